// round 2
// baseline (speedup 1.0000x reference)
#include <cuda_runtime.h>
#include <math.h>

#define D_MODEL   2048
#define NUM_HEADS 16
#define HEAD_DIM  128
#define BATCH     2
#define SEQ       2048
#define M_TOTAL   (BATCH * SEQ)   // 4096

// ---------------- scratch (static device globals: no allocation allowed) ----
__device__ float g_Q[M_TOTAL * D_MODEL];
__device__ float g_K[M_TOTAL * D_MODEL];
__device__ float g_V[M_TOTAL * D_MODEL];
__device__ float g_CTX[M_TOTAL * D_MODEL];

// ============================================================================
// GEMM (NT): C[m,n] = sum_d A[m,d] * B[n,d]
// A: [M, K] row-major, B: [N, K] row-major (i.e. computes A @ B^T)
// Tiles: 128x128x16, 256 threads, 8x8 per thread, fp32.
// Smem stride padded to 132 words -> 2-way max conflicts, float4-aligned.
// ============================================================================
#define GBM 128
#define GBN 128
#define GBK 16
#define GS  132   // padded smem row stride (words); 132*4=528 bytes (16B mult)

__global__ __launch_bounds__(256)
void gemm_nt_kernel(const float* __restrict__ A,
                    const float* __restrict__ B,
                    float* __restrict__ C,
                    int M, int N, int K)
{
    __shared__ float As[GBK * GS];
    __shared__ float Bs[GBK * GS];

    const int tid  = threadIdx.x;
    const int bRow = blockIdx.y * GBM;
    const int bCol = blockIdx.x * GBN;
    const int ty   = tid >> 4;        // 0..15
    const int tx   = tid & 15;        // 0..15

    // loader: thread t -> rows (t/4, t/4+64), float4 column t%4
    const int lr = tid >> 2;          // 0..63
    const int lc = tid & 3;           // 0..3
    const float* Aptr = A + (size_t)(bRow + lr) * K + lc * 4;
    const float* Bptr = B + (size_t)(bCol + lr) * K + lc * 4;

    float acc[8][8] = {};

    for (int k0 = 0; k0 < K; k0 += GBK) {
#pragma unroll
        for (int i = 0; i < 2; i++) {
            const int r = lr + i * 64;
            float4 a = *(const float4*)(Aptr + (size_t)(i * 64) * K + k0);
            As[(lc * 4 + 0) * GS + r] = a.x;
            As[(lc * 4 + 1) * GS + r] = a.y;
            As[(lc * 4 + 2) * GS + r] = a.z;
            As[(lc * 4 + 3) * GS + r] = a.w;
            float4 b = *(const float4*)(Bptr + (size_t)(i * 64) * K + k0);
            Bs[(lc * 4 + 0) * GS + r] = b.x;
            Bs[(lc * 4 + 1) * GS + r] = b.y;
            Bs[(lc * 4 + 2) * GS + r] = b.z;
            Bs[(lc * 4 + 3) * GS + r] = b.w;
        }
        __syncthreads();

#pragma unroll
        for (int k = 0; k < GBK; k++) {
            float ar[8], br[8];
            // 16B-aligned vector loads (GS*4 and ty*8*4 are multiples of 16)
            *(float4*)(ar)     = *(const float4*)(&As[k * GS + ty * 8]);
            *(float4*)(ar + 4) = *(const float4*)(&As[k * GS + ty * 8 + 4]);
            *(float4*)(br)     = *(const float4*)(&Bs[k * GS + tx * 8]);
            *(float4*)(br + 4) = *(const float4*)(&Bs[k * GS + tx * 8 + 4]);
#pragma unroll
            for (int i = 0; i < 8; i++)
#pragma unroll
                for (int j = 0; j < 8; j++)
                    acc[i][j] += ar[i] * br[j];
        }
        __syncthreads();
    }

#pragma unroll
    for (int i = 0; i < 8; i++) {
        float* Crow = C + (size_t)(bRow + ty * 8 + i) * N + bCol + tx * 8;
        *(float4*)(Crow)     = *(const float4*)(&acc[i][0]);
        *(float4*)(Crow + 4) = *(const float4*)(&acc[i][4]);
    }
}

// ============================================================================
// Causal flash attention, fp32.
// Grid: (SEQ/64, BATCH*NUM_HEADS), 256 threads.
// Q/K/V layout in gmem: [B, S, H, Dh] (i.e. the [B*S, D_MODEL] GEMM output).
// Per block: 64 queries x full head. Tk=64 key tiles, online softmax.
// K stored d-major (transposed) in smem -> conflict-free score loop.
// Output written to CTX in [B, S, H, Dh] so the O-projection is a plain GEMM.
// ============================================================================
#define TQ 64
#define TK 64
#define QS 132            // Qs/Vs row stride (words), float4-aligned
#define KST (TK + 1)      // Kst row stride (d-major): 65
#define PS 68             // Ps row stride

#define FLASH_SMEM_WORDS (TQ*QS /*Qs*/ + HEAD_DIM*KST /*Kst*/ + TK*QS /*Vs*/ \
                          + TQ*PS /*Ps*/ + TQ /*alpha*/ + TQ /*linv*/)
#define FLASH_SMEM_BYTES (FLASH_SMEM_WORDS * 4)

__global__ __launch_bounds__(256)
void flash_attn_kernel(const float* __restrict__ Q,
                       const float* __restrict__ K,
                       const float* __restrict__ V,
                       float* __restrict__ O)
{
    extern __shared__ float sm[];
    float* Qs      = sm;                       // [TQ][QS]
    float* Kst     = Qs  + TQ * QS;            // [HEAD_DIM][KST]  (d-major)
    float* Vs      = Kst + HEAD_DIM * KST;     // [TK][QS]
    float* Ps      = Vs  + TK * QS;            // [TQ][PS]
    float* alpha_s = Ps  + TQ * PS;            // [TQ]
    float* linv_s  = alpha_s + TQ;             // [TQ]

    const int tid = threadIdx.x;
    const int qt  = blockIdx.x;
    const int bh  = blockIdx.y;
    const int b   = bh / NUM_HEADS;
    const int h   = bh % NUM_HEADS;
    const int q0  = qt * TQ;
    const float scale = 0.08838834764831845f;  // 1/sqrt(128)

    const size_t base = (size_t)b * SEQ * D_MODEL + (size_t)h * HEAD_DIM;
    const float* Qbase = Q + base;
    const float* Kbase = K + base;
    const float* Vbase = V + base;
    float*       Obase = O + base;

    const int ty = tid >> 4;   // 0..15 -> 4 q-rows each
    const int tx = tid & 15;   // 0..15 -> 4 k-cols (scores) / 8 d-cols (PV)

    // ---- load Q tile (64 rows x 128 floats = 2048 float4) ----
    for (int i = tid; i < TQ * 32; i += 256) {
        const int r = i >> 5, c4 = i & 31;
        float4 v4 = *(const float4*)(Qbase + (size_t)(q0 + r) * D_MODEL + c4 * 4);
        *(float4*)(Qs + r * QS + c4 * 4) = v4;
    }

    float acc[4][8] = {};
    float m_run = -INFINITY, l_run = 0.f;

    for (int kt = 0; kt <= qt; kt++) {
        __syncthreads();   // previous PV done; (iter 0: pairs with post-load sync)
        const int k0 = kt * TK;

        // ---- load K tile transposed (d-major) + V tile ----
        for (int i = tid; i < TK * 32; i += 256) {
            const int r = i >> 5, c4 = i & 31;
            float4 kx = *(const float4*)(Kbase + (size_t)(k0 + r) * D_MODEL + c4 * 4);
            const int d0 = c4 * 4;
            Kst[(d0 + 0) * KST + r] = kx.x;
            Kst[(d0 + 1) * KST + r] = kx.y;
            Kst[(d0 + 2) * KST + r] = kx.z;
            Kst[(d0 + 3) * KST + r] = kx.w;
            float4 vx = *(const float4*)(Vbase + (size_t)(k0 + r) * D_MODEL + c4 * 4);
            *(float4*)(Vs + r * QS + c4 * 4) = vx;
        }
        __syncthreads();

        // ---- scores: each thread 4 q-rows x 4 k-cols, dot over 128 ----
        float s[4][4] = {};
#pragma unroll 4
        for (int d = 0; d < HEAD_DIM; d++) {
            float qv[4], kv[4];
#pragma unroll
            for (int i = 0; i < 4; i++) qv[i] = Qs[(ty * 4 + i) * QS + d];
#pragma unroll
            for (int j = 0; j < 4; j++) kv[j] = Kst[d * KST + tx * 4 + j];
#pragma unroll
            for (int i = 0; i < 4; i++)
#pragma unroll
                for (int j = 0; j < 4; j++)
                    s[i][j] += qv[i] * kv[j];
        }
        const bool diag = (kt == qt);
#pragma unroll
        for (int i = 0; i < 4; i++)
#pragma unroll
            for (int j = 0; j < 4; j++) {
                float val = s[i][j] * scale;
                if (diag && (k0 + tx * 4 + j) > (q0 + ty * 4 + i)) val = -INFINITY;
                Ps[(ty * 4 + i) * PS + tx * 4 + j] = val;
            }
        __syncthreads();

        // ---- online softmax stats: one thread per q-row ----
        if (tid < TQ) {
            float* row = Ps + tid * PS;
            float mt = -INFINITY;
#pragma unroll 8
            for (int k = 0; k < TK; k++) mt = fmaxf(mt, row[k]);
            const float m_new = fmaxf(m_run, mt);
            const float a = __expf(m_run - m_new);   // -inf -> 0 on first tile
            float sum = 0.f;
#pragma unroll 8
            for (int k = 0; k < TK; k++) {
                float p = __expf(row[k] - m_new);
                row[k] = p;
                sum += p;
            }
            l_run = l_run * a + sum;
            m_run = m_new;
            alpha_s[tid] = a;
        }
        __syncthreads();

        // ---- rescale accumulator + PV: rows ty*4.., cols tx*8.. ----
        float a_i[4];
#pragma unroll
        for (int i = 0; i < 4; i++) a_i[i] = alpha_s[ty * 4 + i];
#pragma unroll
        for (int i = 0; i < 4; i++)
#pragma unroll
            for (int c = 0; c < 8; c++) acc[i][c] *= a_i[i];

#pragma unroll 2
        for (int k = 0; k < TK; k++) {
            float p[4], vv[8];
#pragma unroll
            for (int i = 0; i < 4; i++) p[i] = Ps[(ty * 4 + i) * PS + k];
            *(float4*)(vv)     = *(const float4*)(&Vs[k * QS + tx * 8]);
            *(float4*)(vv + 4) = *(const float4*)(&Vs[k * QS + tx * 8 + 4]);
#pragma unroll
            for (int i = 0; i < 4; i++)
#pragma unroll
                for (int c = 0; c < 8; c++)
                    acc[i][c] += p[i] * vv[c];
        }
    }

    if (tid < TQ) linv_s[tid] = 1.f / l_run;
    __syncthreads();

#pragma unroll
    for (int i = 0; i < 4; i++) {
        const float li = linv_s[ty * 4 + i];
        float* orow = Obase + (size_t)(q0 + ty * 4 + i) * D_MODEL + tx * 8;
        float o[8];
#pragma unroll
        for (int c = 0; c < 8; c++) o[c] = acc[i][c] * li;
        *(float4*)(orow)     = *(const float4*)(&o[0]);
        *(float4*)(orow + 4) = *(const float4*)(&o[4]);
    }
}

// ============================================================================
// launch
// ============================================================================
extern "C" void kernel_launch(void* const* d_in, const int* in_sizes, int n_in,
                              void* d_out, int out_size)
{
    const float* x  = (const float*)d_in[0];
    const float* wq = (const float*)d_in[1];
    const float* wk = (const float*)d_in[2];
    const float* wv = (const float*)d_in[3];
    const float* wo = (const float*)d_in[4];
    float* out = (float*)d_out;

    float *Qb, *Kb, *Vb, *Cb;
    cudaGetSymbolAddress((void**)&Qb, g_Q);
    cudaGetSymbolAddress((void**)&Kb, g_K);
    cudaGetSymbolAddress((void**)&Vb, g_V);
    cudaGetSymbolAddress((void**)&Cb, g_CTX);

    dim3 gg(D_MODEL / GBN, M_TOTAL / GBM);   // (16, 32)

    gemm_nt_kernel<<<gg, 256>>>(x, wq, Qb, M_TOTAL, D_MODEL, D_MODEL);
    gemm_nt_kernel<<<gg, 256>>>(x, wk, Kb, M_TOTAL, D_MODEL, D_MODEL);
    gemm_nt_kernel<<<gg, 256>>>(x, wv, Vb, M_TOTAL, D_MODEL, D_MODEL);

    cudaFuncSetAttribute(flash_attn_kernel,
                         cudaFuncAttributeMaxDynamicSharedMemorySize,
                         FLASH_SMEM_BYTES);
    flash_attn_kernel<<<dim3(SEQ / TQ, BATCH * NUM_HEADS), 256,
                        FLASH_SMEM_BYTES>>>(Qb, Kb, Vb, Cb);

    gemm_nt_kernel<<<gg, 256>>>(Cb, wo, out, M_TOTAL, D_MODEL, D_MODEL);
}

// round 4
// speedup vs baseline: 1.4620x; 1.4620x over previous
#include <cuda_runtime.h>
#include <cuda_bf16.h>
#include <cstdint>
#include <math.h>

#define D_MODEL   2048
#define NUM_HEADS 16
#define HEAD_DIM  128
#define BATCH     2
#define SEQ       2048
#define M_TOTAL   (BATCH * SEQ)   // 4096

// ---------------- scratch (static device globals: no allocation allowed) ----
__device__ float g_Q[M_TOTAL * D_MODEL];
__device__ float g_K[M_TOTAL * D_MODEL];
__device__ float g_V[M_TOTAL * D_MODEL];
__device__ float g_CTX[M_TOTAL * D_MODEL];
// bf16 hi/lo split buffers (A side reused for x then CTX; B side per-weight)
__device__ __nv_bfloat16 g_xh[M_TOTAL * D_MODEL];
__device__ __nv_bfloat16 g_xl[M_TOTAL * D_MODEL];
__device__ __nv_bfloat16 g_wh[D_MODEL * D_MODEL];
__device__ __nv_bfloat16 g_wl[D_MODEL * D_MODEL];

// ============================================================================
// helpers
// ============================================================================
__device__ __forceinline__ uint32_t smem_u32(const void* p) {
    uint32_t a;
    asm("{ .reg .u64 t; cvta.to.shared.u64 t, %1; cvt.u32.u64 %0, t; }"
        : "=r"(a) : "l"(p));
    return a;
}
#define SW128(o) ((o) ^ (((o) >> 3) & 0x70))

__device__ __forceinline__ void ldsm4(uint32_t* r, uint32_t addr) {
    asm volatile("ldmatrix.sync.aligned.m8n8.x4.shared.b16 {%0,%1,%2,%3}, [%4];"
                 : "=r"(r[0]), "=r"(r[1]), "=r"(r[2]), "=r"(r[3]) : "r"(addr));
}
__device__ __forceinline__ void mma16816(float* d, const uint32_t* a,
                                         const uint32_t* b) {
    asm volatile(
        "mma.sync.aligned.m16n8k16.row.col.f32.bf16.bf16.f32 "
        "{%0,%1,%2,%3}, {%4,%5,%6,%7}, {%8,%9}, {%0,%1,%2,%3};"
        : "+f"(d[0]), "+f"(d[1]), "+f"(d[2]), "+f"(d[3])
        : "r"(a[0]), "r"(a[1]), "r"(a[2]), "r"(a[3]), "r"(b[0]), "r"(b[1]));
}

// ============================================================================
// fp32 -> (bf16 hi, bf16 lo) split, vectorized
// ============================================================================
__global__ __launch_bounds__(256)
void split_kernel(const float4* __restrict__ src, uint2* __restrict__ hi,
                  uint2* __restrict__ lo, int n4)
{
    int i = blockIdx.x * blockDim.x + threadIdx.x;
    if (i >= n4) return;
    float4 x = src[i];
    __nv_bfloat16 h0 = __float2bfloat16(x.x), h1 = __float2bfloat16(x.y);
    __nv_bfloat16 h2 = __float2bfloat16(x.z), h3 = __float2bfloat16(x.w);
    __nv_bfloat16 l0 = __float2bfloat16(x.x - __bfloat162float(h0));
    __nv_bfloat16 l1 = __float2bfloat16(x.y - __bfloat162float(h1));
    __nv_bfloat16 l2 = __float2bfloat16(x.z - __bfloat162float(h2));
    __nv_bfloat16 l3 = __float2bfloat16(x.w - __bfloat162float(h3));
    __nv_bfloat162 hp0, hp1, lp0, lp1;
    hp0.x = h0; hp0.y = h1; hp1.x = h2; hp1.y = h3;
    lp0.x = l0; lp0.y = l1; lp1.x = l2; lp1.y = l3;
    uint2 ho, lv;
    ho.x = *(uint32_t*)&hp0; ho.y = *(uint32_t*)&hp1;
    lv.x = *(uint32_t*)&lp0; lv.y = *(uint32_t*)&lp1;
    hi[i] = ho;
    lo[i] = lv;
}

// ============================================================================
// Tensor-core GEMM (NT) via mma.sync bf16 + 3-term compensation:
//   C[m,n] = sum_k A[m,k]*B[n,k]  ~=  Ah*Bh + Al*Bh + Ah*Bl  (fp32 accum)
// CTA tile 128x128, K chunk 64. 8 warps, warp tile 64x32.
// Smem tiles [128 rows][64 bf16] = 128B rows, SW128 swizzle (ldmatrix
// conflict-free). 64KB smem total.
// ============================================================================
#define TM 128
#define TN 128
#define TKF 64
#define NCHUNK (D_MODEL / TKF)   // 32
#define TILE_B 16384             // 128 x 128B
#define SM_AH  0
#define SM_AL  (SM_AH + TILE_B)
#define SM_BH  (SM_AL + TILE_B)
#define SM_BL  (SM_BH + TILE_B)
#define GEMM_SMEM (4 * TILE_B)   // 65536

__global__ __launch_bounds__(256)
void gemm_mma_kernel(const __nv_bfloat16* __restrict__ Ah,
                     const __nv_bfloat16* __restrict__ Al,
                     const __nv_bfloat16* __restrict__ Bh,
                     const __nv_bfloat16* __restrict__ Bl,
                     float* __restrict__ C)
{
    extern __shared__ char smc[];
    const uint32_t sb = smem_u32(smc);
    const int tid  = threadIdx.x;
    const int wid  = tid >> 5;
    const int lane = tid & 31;
    const int bN = blockIdx.x * TN;
    const int bM = blockIdx.y * TM;
    const int wm = (wid & 1) * 64;    // warp M offset in tile
    const int wn = (wid >> 1) * 32;   // warp N offset in tile

    // ldmatrix per-lane row/k-half mapping
    // A (x4: m0-7/k0-7, m8-15/k0-7, m0-7/k8-15, m8-15/k8-15)
    const int a_row = wm + (lane & 15);
    const int a_kh  = (lane >> 4) * 8;
    // B (x4 over 2 n-frags: (j0,k0-7),(j0,k8-15),(j1,k0-7),(j1,k8-15))
    const int b_jg  = (lane >> 4);          // 0/1: n-frag within pair
    const int b_kh  = ((lane >> 3) & 1) * 8;
    const int b_r8  = lane & 7;

    const __nv_bfloat16* srcs[4] = {
        Ah + (size_t)bM * D_MODEL, Al + (size_t)bM * D_MODEL,
        Bh + (size_t)bN * D_MODEL, Bl + (size_t)bN * D_MODEL };
    const uint32_t toff[4] = { SM_AH, SM_AL, SM_BH, SM_BL };

    float acc[4][4][4] = {};   // [m-frag][n-frag][4]

    for (int c = 0; c < NCHUNK; c++) {
        const int k0 = c * TKF;
        // ---- load 4 tiles (each 1024 16B-vectors; 256 thr x 4 iters) ----
#pragma unroll
        for (int t = 0; t < 4; t++) {
            const __nv_bfloat16* s = srcs[t] + k0;
#pragma unroll
            for (int it = 0; it < 4; it++) {
                const int vec = tid + it * 256;
                const int r = vec >> 3, v = vec & 7;
                uint4 val = *(const uint4*)(s + (size_t)r * D_MODEL + v * 8);
                *(uint4*)(smc + toff[t] + SW128((uint32_t)(r * 128 + v * 16))) = val;
            }
        }
        __syncthreads();

        // ---- compute: 4 k16-steps ----
#pragma unroll
        for (int ks = 0; ks < 4; ks++) {
            const int k16 = ks * 16;
            uint32_t ahf[4][4], alf[4][4], bf[4][2];

            // Ah fragments
#pragma unroll
            for (int i = 0; i < 4; i++)
                ldsm4(ahf[i], sb + SM_AH +
                      SW128((uint32_t)((a_row + i * 16) * 128 + (k16 + a_kh) * 2)));
            // Bh fragments (2 x4 loads covering n-frags 0..3)
#pragma unroll
            for (int p = 0; p < 2; p++) {
                uint32_t r[4];
                const int jr = wn + (p * 2 + b_jg) * 8 + b_r8;
                ldsm4(r, sb + SM_BH +
                      SW128((uint32_t)(jr * 128 + (k16 + b_kh) * 2)));
                bf[p * 2 + 0][0] = r[0]; bf[p * 2 + 0][1] = r[1];
                bf[p * 2 + 1][0] = r[2]; bf[p * 2 + 1][1] = r[3];
            }
            // term 1: Ah * Bh
#pragma unroll
            for (int i = 0; i < 4; i++)
#pragma unroll
                for (int j = 0; j < 4; j++)
                    mma16816(acc[i][j], ahf[i], bf[j]);

            // Al fragments, term 2: Al * Bh
#pragma unroll
            for (int i = 0; i < 4; i++)
                ldsm4(alf[i], sb + SM_AL +
                      SW128((uint32_t)((a_row + i * 16) * 128 + (k16 + a_kh) * 2)));
#pragma unroll
            for (int i = 0; i < 4; i++)
#pragma unroll
                for (int j = 0; j < 4; j++)
                    mma16816(acc[i][j], alf[i], bf[j]);

            // Bl fragments (overwrite bf), term 3: Ah * Bl
#pragma unroll
            for (int p = 0; p < 2; p++) {
                uint32_t r[4];
                const int jr = wn + (p * 2 + b_jg) * 8 + b_r8;
                ldsm4(r, sb + SM_BL +
                      SW128((uint32_t)(jr * 128 + (k16 + b_kh) * 2)));
                bf[p * 2 + 0][0] = r[0]; bf[p * 2 + 0][1] = r[1];
                bf[p * 2 + 1][0] = r[2]; bf[p * 2 + 1][1] = r[3];
            }
#pragma unroll
            for (int i = 0; i < 4; i++)
#pragma unroll
                for (int j = 0; j < 4; j++)
                    mma16816(acc[i][j], ahf[i], bf[j]);
        }
        __syncthreads();
    }

    // ---- epilogue: D frag -> gmem (row = lane/4 (+8), col = (lane%4)*2) ----
    const int er = bM + wm + (lane >> 2);
    const int ec = bN + wn + (lane & 3) * 2;
#pragma unroll
    for (int i = 0; i < 4; i++)
#pragma unroll
        for (int j = 0; j < 4; j++) {
            float* p0 = C + (size_t)(er + i * 16) * D_MODEL + ec + j * 8;
            float* p1 = C + (size_t)(er + i * 16 + 8) * D_MODEL + ec + j * 8;
            *(float2*)p0 = make_float2(acc[i][j][0], acc[i][j][1]);
            *(float2*)p1 = make_float2(acc[i][j][2], acc[i][j][3]);
        }
}

// ============================================================================
// Causal flash attention, fp32 (unchanged from passing R1 kernel)
// ============================================================================
#define TQ 64
#define TK 64
#define QS 132
#define KST (TK + 1)
#define PS 68

#define FLASH_SMEM_WORDS (TQ*QS + HEAD_DIM*KST + TK*QS + TQ*PS + TQ + TQ)
#define FLASH_SMEM_BYTES (FLASH_SMEM_WORDS * 4)

__global__ __launch_bounds__(256)
void flash_attn_kernel(const float* __restrict__ Q,
                       const float* __restrict__ K,
                       const float* __restrict__ V,
                       float* __restrict__ O)
{
    extern __shared__ float sm[];
    float* Qs      = sm;
    float* Kst     = Qs  + TQ * QS;
    float* Vs      = Kst + HEAD_DIM * KST;
    float* Ps      = Vs  + TK * QS;
    float* alpha_s = Ps  + TQ * PS;
    float* linv_s  = alpha_s + TQ;

    const int tid = threadIdx.x;
    const int qt  = blockIdx.x;
    const int bh  = blockIdx.y;
    const int b   = bh / NUM_HEADS;
    const int h   = bh % NUM_HEADS;
    const int q0  = qt * TQ;
    const float scale = 0.08838834764831845f;

    const size_t base = (size_t)b * SEQ * D_MODEL + (size_t)h * HEAD_DIM;
    const float* Qbase = Q + base;
    const float* Kbase = K + base;
    const float* Vbase = V + base;
    float*       Obase = O + base;

    const int ty = tid >> 4;
    const int tx = tid & 15;

    for (int i = tid; i < TQ * 32; i += 256) {
        const int r = i >> 5, c4 = i & 31;
        float4 v4 = *(const float4*)(Qbase + (size_t)(q0 + r) * D_MODEL + c4 * 4);
        *(float4*)(Qs + r * QS + c4 * 4) = v4;
    }

    float acc[4][8] = {};
    float m_run = -INFINITY, l_run = 0.f;

    for (int kt = 0; kt <= qt; kt++) {
        __syncthreads();
        const int k0 = kt * TK;

        for (int i = tid; i < TK * 32; i += 256) {
            const int r = i >> 5, c4 = i & 31;
            float4 kx = *(const float4*)(Kbase + (size_t)(k0 + r) * D_MODEL + c4 * 4);
            const int d0 = c4 * 4;
            Kst[(d0 + 0) * KST + r] = kx.x;
            Kst[(d0 + 1) * KST + r] = kx.y;
            Kst[(d0 + 2) * KST + r] = kx.z;
            Kst[(d0 + 3) * KST + r] = kx.w;
            float4 vx = *(const float4*)(Vbase + (size_t)(k0 + r) * D_MODEL + c4 * 4);
            *(float4*)(Vs + r * QS + c4 * 4) = vx;
        }
        __syncthreads();

        float s[4][4] = {};
#pragma unroll 4
        for (int d = 0; d < HEAD_DIM; d++) {
            float qv[4], kv[4];
#pragma unroll
            for (int i = 0; i < 4; i++) qv[i] = Qs[(ty * 4 + i) * QS + d];
#pragma unroll
            for (int j = 0; j < 4; j++) kv[j] = Kst[d * KST + tx * 4 + j];
#pragma unroll
            for (int i = 0; i < 4; i++)
#pragma unroll
                for (int j = 0; j < 4; j++)
                    s[i][j] += qv[i] * kv[j];
        }
        const bool diag = (kt == qt);
#pragma unroll
        for (int i = 0; i < 4; i++)
#pragma unroll
            for (int j = 0; j < 4; j++) {
                float val = s[i][j] * scale;
                if (diag && (k0 + tx * 4 + j) > (q0 + ty * 4 + i)) val = -INFINITY;
                Ps[(ty * 4 + i) * PS + tx * 4 + j] = val;
            }
        __syncthreads();

        if (tid < TQ) {
            float* row = Ps + tid * PS;
            float mt = -INFINITY;
#pragma unroll 8
            for (int k = 0; k < TK; k++) mt = fmaxf(mt, row[k]);
            const float m_new = fmaxf(m_run, mt);
            const float a = __expf(m_run - m_new);
            float sum = 0.f;
#pragma unroll 8
            for (int k = 0; k < TK; k++) {
                float p = __expf(row[k] - m_new);
                row[k] = p;
                sum += p;
            }
            l_run = l_run * a + sum;
            m_run = m_new;
            alpha_s[tid] = a;
        }
        __syncthreads();

        float a_i[4];
#pragma unroll
        for (int i = 0; i < 4; i++) a_i[i] = alpha_s[ty * 4 + i];
#pragma unroll
        for (int i = 0; i < 4; i++)
#pragma unroll
            for (int c = 0; c < 8; c++) acc[i][c] *= a_i[i];

#pragma unroll 2
        for (int k = 0; k < TK; k++) {
            float p[4], vv[8];
#pragma unroll
            for (int i = 0; i < 4; i++) p[i] = Ps[(ty * 4 + i) * PS + k];
            *(float4*)(vv)     = *(const float4*)(&Vs[k * QS + tx * 8]);
            *(float4*)(vv + 4) = *(const float4*)(&Vs[k * QS + tx * 8 + 4]);
#pragma unroll
            for (int i = 0; i < 4; i++)
#pragma unroll
                for (int c = 0; c < 8; c++)
                    acc[i][c] += p[i] * vv[c];
        }
    }

    if (tid < TQ) linv_s[tid] = 1.f / l_run;
    __syncthreads();

#pragma unroll
    for (int i = 0; i < 4; i++) {
        const float li = linv_s[ty * 4 + i];
        float* orow = Obase + (size_t)(q0 + ty * 4 + i) * D_MODEL + tx * 8;
        float o[8];
#pragma unroll
        for (int c = 0; c < 8; c++) o[c] = acc[i][c] * li;
        *(float4*)(orow)     = *(const float4*)(&o[0]);
        *(float4*)(orow + 4) = *(const float4*)(&o[4]);
    }
}

// ============================================================================
// launch
// ============================================================================
extern "C" void kernel_launch(void* const* d_in, const int* in_sizes, int n_in,
                              void* d_out, int out_size)
{
    const float* x  = (const float*)d_in[0];
    const float* wq = (const float*)d_in[1];
    const float* wk = (const float*)d_in[2];
    const float* wv = (const float*)d_in[3];
    const float* wo = (const float*)d_in[4];
    float* out = (float*)d_out;

    float *Qb, *Kb, *Vb, *Cb;
    cudaGetSymbolAddress((void**)&Qb, g_Q);
    cudaGetSymbolAddress((void**)&Kb, g_K);
    cudaGetSymbolAddress((void**)&Vb, g_V);
    cudaGetSymbolAddress((void**)&Cb, g_CTX);
    __nv_bfloat16 *xh, *xl, *wh, *wl;
    cudaGetSymbolAddress((void**)&xh, g_xh);
    cudaGetSymbolAddress((void**)&xl, g_xl);
    cudaGetSymbolAddress((void**)&wh, g_wh);
    cudaGetSymbolAddress((void**)&wl, g_wl);

    cudaFuncSetAttribute(gemm_mma_kernel,
                         cudaFuncAttributeMaxDynamicSharedMemorySize, GEMM_SMEM);
    cudaFuncSetAttribute(flash_attn_kernel,
                         cudaFuncAttributeMaxDynamicSharedMemorySize, FLASH_SMEM_BYTES);

    const int nx4 = M_TOTAL * D_MODEL / 4;
    const int nw4 = D_MODEL * D_MODEL / 4;
    dim3 gg(D_MODEL / TN, M_TOTAL / TM);     // (16, 32)

    // x -> hi/lo
    split_kernel<<<(nx4 + 255) / 256, 256>>>((const float4*)x, (uint2*)xh, (uint2*)xl, nx4);

    // Q/K/V projections
    split_kernel<<<(nw4 + 255) / 256, 256>>>((const float4*)wq, (uint2*)wh, (uint2*)wl, nw4);
    gemm_mma_kernel<<<gg, 256, GEMM_SMEM>>>(xh, xl, wh, wl, Qb);
    split_kernel<<<(nw4 + 255) / 256, 256>>>((const float4*)wk, (uint2*)wh, (uint2*)wl, nw4);
    gemm_mma_kernel<<<gg, 256, GEMM_SMEM>>>(xh, xl, wh, wl, Kb);
    split_kernel<<<(nw4 + 255) / 256, 256>>>((const float4*)wv, (uint2*)wh, (uint2*)wl, nw4);
    gemm_mma_kernel<<<gg, 256, GEMM_SMEM>>>(xh, xl, wh, wl, Vb);

    // attention
    flash_attn_kernel<<<dim3(SEQ / TQ, BATCH * NUM_HEADS), 256,
                        FLASH_SMEM_BYTES>>>(Qb, Kb, Vb, Cb);

    // output projection
    split_kernel<<<(nx4 + 255) / 256, 256>>>((const float4*)Cb, (uint2*)xh, (uint2*)xl, nx4);
    split_kernel<<<(nw4 + 255) / 256, 256>>>((const float4*)wo, (uint2*)wh, (uint2*)wl, nw4);
    gemm_mma_kernel<<<gg, 256, GEMM_SMEM>>>(xh, xl, wh, wl, out);
}

// round 5
// speedup vs baseline: 2.1085x; 1.4422x over previous
#include <cuda_runtime.h>
#include <cuda_bf16.h>
#include <cstdint>
#include <math.h>

#define D_MODEL   2048
#define NUM_HEADS 16
#define HEAD_DIM  128
#define BATCH     2
#define SEQ       2048
#define M_TOTAL   (BATCH * SEQ)   // 4096

// ---------------- scratch (static device globals: no allocation allowed) ----
__device__ __nv_bfloat16 g_xh[M_TOTAL * D_MODEL];
__device__ __nv_bfloat16 g_xl[M_TOTAL * D_MODEL];
__device__ __nv_bfloat16 g_wh[D_MODEL * D_MODEL];
__device__ __nv_bfloat16 g_wl[D_MODEL * D_MODEL];
__device__ __nv_bfloat16 g_Qh[M_TOTAL * D_MODEL];
__device__ __nv_bfloat16 g_Ql[M_TOTAL * D_MODEL];
__device__ __nv_bfloat16 g_Kh[M_TOTAL * D_MODEL];
__device__ __nv_bfloat16 g_Kl[M_TOTAL * D_MODEL];
__device__ __nv_bfloat16 g_Vh[M_TOTAL * D_MODEL];
__device__ __nv_bfloat16 g_Vl[M_TOTAL * D_MODEL];
__device__ __nv_bfloat16 g_Ch[M_TOTAL * D_MODEL];
__device__ __nv_bfloat16 g_Cl[M_TOTAL * D_MODEL];

// ============================================================================
// helpers
// ============================================================================
__device__ __forceinline__ uint32_t smem_u32(const void* p) {
    uint32_t a;
    asm("{ .reg .u64 t; cvta.to.shared.u64 t, %1; cvt.u32.u64 %0, t; }"
        : "=r"(a) : "l"(p));
    return a;
}
#define SW128(o) ((o) ^ (((o) >> 3) & 0x70))

__device__ __forceinline__ void ldsm4(uint32_t* r, uint32_t addr) {
    asm volatile("ldmatrix.sync.aligned.m8n8.x4.shared.b16 {%0,%1,%2,%3}, [%4];"
                 : "=r"(r[0]), "=r"(r[1]), "=r"(r[2]), "=r"(r[3]) : "r"(addr));
}
__device__ __forceinline__ void ldsm4t(uint32_t* r, uint32_t addr) {
    asm volatile("ldmatrix.sync.aligned.m8n8.x4.trans.shared.b16 {%0,%1,%2,%3}, [%4];"
                 : "=r"(r[0]), "=r"(r[1]), "=r"(r[2]), "=r"(r[3]) : "r"(addr));
}
__device__ __forceinline__ void mma16816(float* d, const uint32_t* a,
                                         const uint32_t* b) {
    asm volatile(
        "mma.sync.aligned.m16n8k16.row.col.f32.bf16.bf16.f32 "
        "{%0,%1,%2,%3}, {%4,%5,%6,%7}, {%8,%9}, {%0,%1,%2,%3};"
        : "+f"(d[0]), "+f"(d[1]), "+f"(d[2]), "+f"(d[3])
        : "r"(a[0]), "r"(a[1]), "r"(a[2]), "r"(a[3]), "r"(b[0]), "r"(b[1]));
}
__device__ __forceinline__ void cpasync16(uint32_t dst, const void* src) {
    asm volatile("cp.async.cg.shared.global [%0], [%1], 16;"
                 :: "r"(dst), "l"(src) : "memory");
}
#define CP_COMMIT() asm volatile("cp.async.commit_group;" ::: "memory")
#define CP_WAIT1()  asm volatile("cp.async.wait_group 1;" ::: "memory")
#define CP_WAIT0()  asm volatile("cp.async.wait_group 0;" ::: "memory")

// fp32 pair -> bf16x2 hi + bf16x2 lo (residual)
__device__ __forceinline__ void split2(float a, float b, uint32_t& hi, uint32_t& lo) {
    __nv_bfloat162 h = __floats2bfloat162_rn(a, b);
    hi = *(uint32_t*)&h;
    float ra = a - __bfloat162float(h.x);
    float rb = b - __bfloat162float(h.y);
    __nv_bfloat162 l = __floats2bfloat162_rn(ra, rb);
    lo = *(uint32_t*)&l;
}

// ============================================================================
// fp32 -> (bf16 hi, bf16 lo) split, vectorized
// ============================================================================
__global__ __launch_bounds__(256)
void split_kernel(const float4* __restrict__ src, uint2* __restrict__ hi,
                  uint2* __restrict__ lo, int n4)
{
    int i = blockIdx.x * blockDim.x + threadIdx.x;
    if (i >= n4) return;
    float4 x = src[i];
    uint2 ho, lv;
    split2(x.x, x.y, ho.x, lv.x);
    split2(x.z, x.w, ho.y, lv.y);
    hi[i] = ho;
    lo[i] = lv;
}

// ============================================================================
// Tensor-core GEMM (NT), 3-term bf16 compensation, cp.async double-buffered.
//   C[m,n] = sum_k A[m,k]*B[n,k] ~= Ah*Bh + Al*Bh + Ah*Bl   (fp32 accum)
// CTA 128x128, K chunk 64, 8 warps (warp 64x32). 2 smem stages x 64KB.
// SPLIT=true: emit C as bf16 hi/lo pair arrays instead of fp32.
// ============================================================================
#define TKF 64
#define NCHUNK (D_MODEL / TKF)     // 32
#define G_STAGE 65536
#define G_AH 0
#define G_AL 16384
#define G_BH 32768
#define G_BL 49152
#define GEMM_SMEM (2 * G_STAGE)    // 131072

template<bool SPLIT>
__global__ __launch_bounds__(256, 1)
void gemm_mma_kernel(const __nv_bfloat16* __restrict__ Ah,
                     const __nv_bfloat16* __restrict__ Al,
                     const __nv_bfloat16* __restrict__ Bh,
                     const __nv_bfloat16* __restrict__ Bl,
                     float* __restrict__ C,
                     __nv_bfloat16* __restrict__ Ch,
                     __nv_bfloat16* __restrict__ Cl)
{
    extern __shared__ char smc[];
    const uint32_t sb = smem_u32(smc);
    const int tid  = threadIdx.x;
    const int wid  = tid >> 5;
    const int lane = tid & 31;
    const int bN = blockIdx.x * 128;
    const int bM = blockIdx.y * 128;
    const int wm = (wid & 1) * 64;
    const int wn = (wid >> 1) * 32;

    const int a_row = wm + (lane & 15);
    const int a_kh  = (lane >> 4) * 8;
    const int b_jg  = (lane >> 4);
    const int b_kh  = ((lane >> 3) & 1) * 8;
    const int b_r8  = lane & 7;

    const __nv_bfloat16* srcs[4] = {
        Ah + (size_t)bM * D_MODEL, Al + (size_t)bM * D_MODEL,
        Bh + (size_t)bN * D_MODEL, Bl + (size_t)bN * D_MODEL };

    // per-thread cp.async mapping: 4 vectors per tile, 4 tiles
    const int lr = tid >> 3;      // not used directly; keep mapping below
    (void)lr;

    auto prefetch = [&](int c, int stage) {
        const int k0 = c * TKF;
        const uint32_t base = sb + stage * G_STAGE;
#pragma unroll
        for (int t = 0; t < 4; t++) {
            const __nv_bfloat16* s = srcs[t] + k0;
#pragma unroll
            for (int it = 0; it < 4; it++) {
                const int vec = tid + it * 256;
                const int r = vec >> 3, v = vec & 7;
                cpasync16(base + t * 16384 + SW128((uint32_t)(r * 128 + v * 16)),
                          s + (size_t)r * D_MODEL + v * 8);
            }
        }
    };

    float acc[4][4][4] = {};

    prefetch(0, 0);
    CP_COMMIT();

    for (int c = 0; c < NCHUNK; c++) {
        if (c + 1 < NCHUNK) { prefetch(c + 1, (c + 1) & 1); CP_COMMIT(); CP_WAIT1(); }
        else                { CP_WAIT0(); }
        __syncthreads();

        const uint32_t st = sb + (c & 1) * G_STAGE;
#pragma unroll
        for (int ks = 0; ks < 4; ks++) {
            const int k16 = ks * 16;
            uint32_t ahf[4][4], alf[4][4], bf[4][2];
#pragma unroll
            for (int i = 0; i < 4; i++)
                ldsm4(ahf[i], st + G_AH +
                      SW128((uint32_t)((a_row + i * 16) * 128 + (k16 + a_kh) * 2)));
#pragma unroll
            for (int p = 0; p < 2; p++) {
                uint32_t r[4];
                const int jr = wn + (p * 2 + b_jg) * 8 + b_r8;
                ldsm4(r, st + G_BH + SW128((uint32_t)(jr * 128 + (k16 + b_kh) * 2)));
                bf[p * 2 + 0][0] = r[0]; bf[p * 2 + 0][1] = r[1];
                bf[p * 2 + 1][0] = r[2]; bf[p * 2 + 1][1] = r[3];
            }
#pragma unroll
            for (int i = 0; i < 4; i++)
#pragma unroll
                for (int j = 0; j < 4; j++)
                    mma16816(acc[i][j], ahf[i], bf[j]);
#pragma unroll
            for (int i = 0; i < 4; i++)
                ldsm4(alf[i], st + G_AL +
                      SW128((uint32_t)((a_row + i * 16) * 128 + (k16 + a_kh) * 2)));
#pragma unroll
            for (int i = 0; i < 4; i++)
#pragma unroll
                for (int j = 0; j < 4; j++)
                    mma16816(acc[i][j], alf[i], bf[j]);
#pragma unroll
            for (int p = 0; p < 2; p++) {
                uint32_t r[4];
                const int jr = wn + (p * 2 + b_jg) * 8 + b_r8;
                ldsm4(r, st + G_BL + SW128((uint32_t)(jr * 128 + (k16 + b_kh) * 2)));
                bf[p * 2 + 0][0] = r[0]; bf[p * 2 + 0][1] = r[1];
                bf[p * 2 + 1][0] = r[2]; bf[p * 2 + 1][1] = r[3];
            }
#pragma unroll
            for (int i = 0; i < 4; i++)
#pragma unroll
                for (int j = 0; j < 4; j++)
                    mma16816(acc[i][j], ahf[i], bf[j]);
        }
        __syncthreads();
    }

    // ---- epilogue ----
    const int er = bM + wm + (lane >> 2);
    const int ec = bN + wn + (lane & 3) * 2;
#pragma unroll
    for (int i = 0; i < 4; i++)
#pragma unroll
        for (int j = 0; j < 4; j++) {
            const size_t o0 = (size_t)(er + i * 16) * D_MODEL + ec + j * 8;
            const size_t o1 = (size_t)(er + i * 16 + 8) * D_MODEL + ec + j * 8;
            if (SPLIT) {
                uint32_t h, l;
                split2(acc[i][j][0], acc[i][j][1], h, l);
                *(uint32_t*)&Ch[o0] = h; *(uint32_t*)&Cl[o0] = l;
                split2(acc[i][j][2], acc[i][j][3], h, l);
                *(uint32_t*)&Ch[o1] = h; *(uint32_t*)&Cl[o1] = l;
            } else {
                *(float2*)&C[o0] = make_float2(acc[i][j][0], acc[i][j][1]);
                *(float2*)&C[o1] = make_float2(acc[i][j][2], acc[i][j][3]);
            }
        }
}

// ============================================================================
// Causal flash attention on tensor cores (mma.sync bf16, 3-term compensated
// on both QK^T and PV). CTA: 128 q-rows x full head; K tile 64. 8 warps,
// warp = 16 q-rows. Inputs bf16 hi/lo; output bf16 hi/lo CTX.
// Smem: Q 4x16KB, K 4x8KB, V 4x8KB = 128KB. Subtiles split head dim 2x64.
// ============================================================================
#define FQ_BASE 0
#define FK_BASE 65536
#define FV_BASE 98304
#define FLASH_SMEM 131072
#define TQF 128
#define TKN 64

__global__ __launch_bounds__(256, 1)
void flash_mma_kernel(const __nv_bfloat16* __restrict__ Qh,
                      const __nv_bfloat16* __restrict__ Ql,
                      const __nv_bfloat16* __restrict__ Kh,
                      const __nv_bfloat16* __restrict__ Kl,
                      const __nv_bfloat16* __restrict__ Vh,
                      const __nv_bfloat16* __restrict__ Vl,
                      __nv_bfloat16* __restrict__ Ch,
                      __nv_bfloat16* __restrict__ Cl)
{
    extern __shared__ char smf[];
    const uint32_t sb = smem_u32(smf);
    const int tid  = threadIdx.x;
    const int wid  = tid >> 5;
    const int lane = tid & 31;

    const int qt = (int)(gridDim.x - 1) - (int)blockIdx.x;  // heavy CTAs first
    const int bh = blockIdx.y;
    const int b  = bh >> 4;
    const int h  = bh & 15;
    const int q0 = qt * TQF;
    const float scale = 0.08838834764831845f;   // 1/sqrt(128)

    const size_t qbase = ((size_t)(b * SEQ + q0)) * D_MODEL + h * HEAD_DIM;
    const size_t kvbase = ((size_t)(b * SEQ)) * D_MODEL + h * HEAD_DIM;

    // ---- load Q tile (hi+lo), subtiles split at d=64 ----
    for (int i = tid; i < TQF * 16; i += 256) {
        const int r = i >> 4, v = i & 15;
        const uint32_t so = (uint32_t)((v >> 3) * 16384) + SW128((uint32_t)(r * 128 + (v & 7) * 16));
        *(uint4*)(smf + FQ_BASE + so) =
            *(const uint4*)(Qh + qbase + (size_t)r * D_MODEL + v * 8);
        *(uint4*)(smf + FQ_BASE + 32768 + so) =
            *(const uint4*)(Ql + qbase + (size_t)r * D_MODEL + v * 8);
    }

    const int wm = wid * 16;
    const int a_row = wm + (lane & 15);
    const int a_kh  = (lane >> 4) * 8;

    float oacc[16][4] = {};
    float m0 = -INFINITY, m1 = -INFINITY, l0 = 0.f, l1 = 0.f;

    const int nkt = 2 * qt + 2;
    for (int kt = 0; kt < nkt; kt++) {
        const int k0 = kt * TKN;
        __syncthreads();   // previous tile's compute done (iter0: pairs with Q-load)
        // ---- load K,V tiles (hi+lo) ----
        for (int i = tid; i < TKN * 16; i += 256) {
            const int r = i >> 4, v = i & 15;
            const size_t g = kvbase + (size_t)(k0 + r) * D_MODEL + v * 8;
            const uint32_t so = (uint32_t)((v >> 3) * 8192) + SW128((uint32_t)(r * 128 + (v & 7) * 16));
            *(uint4*)(smf + FK_BASE + so)         = *(const uint4*)(Kh + g);
            *(uint4*)(smf + FK_BASE + 16384 + so) = *(const uint4*)(Kl + g);
            *(uint4*)(smf + FV_BASE + so)         = *(const uint4*)(Vh + g);
            *(uint4*)(smf + FV_BASE + 16384 + so) = *(const uint4*)(Vl + g);
        }
        __syncthreads();

        // ---- S = Q K^T (3-term) ----
        float sacc[8][4] = {};
#pragma unroll
        for (int s = 0; s < 8; s++) {
            const int sub = s >> 2, kb = (s & 3) * 16;
            const uint32_t qoff = (uint32_t)(sub * 16384) +
                SW128((uint32_t)(a_row * 128 + (kb + a_kh) * 2));
            uint32_t qhf[4], qlf[4], kf[8][2];
            ldsm4(qhf, sb + FQ_BASE + qoff);
            ldsm4(qlf, sb + FQ_BASE + 32768 + qoff);
#pragma unroll
            for (int p = 0; p < 4; p++) {
                uint32_t r[4];
                const int jr = (p * 2 + (lane >> 4)) * 8 + (lane & 7);
                ldsm4(r, sb + FK_BASE + sub * 8192 +
                      SW128((uint32_t)(jr * 128 + (kb + ((lane >> 3) & 1) * 8) * 2)));
                kf[p * 2 + 0][0] = r[0]; kf[p * 2 + 0][1] = r[1];
                kf[p * 2 + 1][0] = r[2]; kf[p * 2 + 1][1] = r[3];
            }
#pragma unroll
            for (int j = 0; j < 8; j++) mma16816(sacc[j], qhf, kf[j]);
#pragma unroll
            for (int j = 0; j < 8; j++) mma16816(sacc[j], qlf, kf[j]);
#pragma unroll
            for (int p = 0; p < 4; p++) {
                uint32_t r[4];
                const int jr = (p * 2 + (lane >> 4)) * 8 + (lane & 7);
                ldsm4(r, sb + FK_BASE + 16384 + sub * 8192 +
                      SW128((uint32_t)(jr * 128 + (kb + ((lane >> 3) & 1) * 8) * 2)));
                kf[p * 2 + 0][0] = r[0]; kf[p * 2 + 0][1] = r[1];
                kf[p * 2 + 1][0] = r[2]; kf[p * 2 + 1][1] = r[3];
            }
#pragma unroll
            for (int j = 0; j < 8; j++) mma16816(sacc[j], qhf, kf[j]);
        }

        // ---- scale + causal mask ----
        const bool needmask = (k0 + TKN - 1) > (q0 + wm);
        const int rl = lane >> 2, cl = (lane & 3) * 2;
#pragma unroll
        for (int j = 0; j < 8; j++)
#pragma unroll
            for (int e = 0; e < 4; e++) {
                float v = sacc[j][e] * scale;
                if (needmask) {
                    const int colg = k0 + 8 * j + cl + (e & 1);
                    const int rowg = q0 + wm + rl + (e >> 1) * 8;
                    if (colg > rowg) v = -INFINITY;
                }
                sacc[j][e] = v;
            }

        // ---- online softmax ----
        float mt0 = -INFINITY, mt1 = -INFINITY;
#pragma unroll
        for (int j = 0; j < 8; j++) {
            mt0 = fmaxf(mt0, fmaxf(sacc[j][0], sacc[j][1]));
            mt1 = fmaxf(mt1, fmaxf(sacc[j][2], sacc[j][3]));
        }
        mt0 = fmaxf(mt0, __shfl_xor_sync(0xFFFFFFFFu, mt0, 1));
        mt0 = fmaxf(mt0, __shfl_xor_sync(0xFFFFFFFFu, mt0, 2));
        mt1 = fmaxf(mt1, __shfl_xor_sync(0xFFFFFFFFu, mt1, 1));
        mt1 = fmaxf(mt1, __shfl_xor_sync(0xFFFFFFFFu, mt1, 2));
        const float mn0 = fmaxf(m0, mt0), mn1 = fmaxf(m1, mt1);
        const float al0 = __expf(m0 - mn0), al1 = __expf(m1 - mn1);
        float s0 = 0.f, s1 = 0.f;
#pragma unroll
        for (int j = 0; j < 8; j++) {
            sacc[j][0] = __expf(sacc[j][0] - mn0); s0 += sacc[j][0];
            sacc[j][1] = __expf(sacc[j][1] - mn0); s0 += sacc[j][1];
            sacc[j][2] = __expf(sacc[j][2] - mn1); s1 += sacc[j][2];
            sacc[j][3] = __expf(sacc[j][3] - mn1); s1 += sacc[j][3];
        }
        s0 += __shfl_xor_sync(0xFFFFFFFFu, s0, 1);
        s0 += __shfl_xor_sync(0xFFFFFFFFu, s0, 2);
        s1 += __shfl_xor_sync(0xFFFFFFFFu, s1, 1);
        s1 += __shfl_xor_sync(0xFFFFFFFFu, s1, 2);
        l0 = l0 * al0 + s0;
        l1 = l1 * al1 + s1;
        m0 = mn0; m1 = mn1;
#pragma unroll
        for (int j = 0; j < 16; j++) {
            oacc[j][0] *= al0; oacc[j][1] *= al0;
            oacc[j][2] *= al1; oacc[j][3] *= al1;
        }

        // ---- O += P V (3-term), V^T frags via ldmatrix.trans ----
#pragma unroll
        for (int s2 = 0; s2 < 4; s2++) {
            uint32_t ph[4], pl[4];
            split2(sacc[2 * s2][0],     sacc[2 * s2][1],     ph[0], pl[0]);
            split2(sacc[2 * s2][2],     sacc[2 * s2][3],     ph[1], pl[1]);
            split2(sacc[2 * s2 + 1][0], sacc[2 * s2 + 1][1], ph[2], pl[2]);
            split2(sacc[2 * s2 + 1][2], sacc[2 * s2 + 1][3], ph[3], pl[3]);
            const int vrow = 16 * s2 + ((lane >> 3) & 1) * 8 + (lane & 7);
#pragma unroll
            for (int p = 0; p < 8; p++) {
                const uint32_t voff = (uint32_t)((p >> 2) * 8192) +
                    SW128((uint32_t)(vrow * 128 + 32 * (p & 3) + (lane >> 4) * 16));
                uint32_t r[4];
                ldsm4t(r, sb + FV_BASE + voff);
                uint32_t b0[2] = { r[0], r[1] }, b1[2] = { r[2], r[3] };
                mma16816(oacc[2 * p],     ph, b0);
                mma16816(oacc[2 * p + 1], ph, b1);
                mma16816(oacc[2 * p],     pl, b0);
                mma16816(oacc[2 * p + 1], pl, b1);
                ldsm4t(r, sb + FV_BASE + 16384 + voff);
                uint32_t c0[2] = { r[0], r[1] }, c1[2] = { r[2], r[3] };
                mma16816(oacc[2 * p],     ph, c0);
                mma16816(oacc[2 * p + 1], ph, c1);
            }
        }
    }

    // ---- epilogue: normalize, split to bf16 hi/lo, store CTX ----
    const float li0 = 1.f / l0, li1 = 1.f / l1;
    const int r0 = q0 + wm + (lane >> 2);
    const int cbase = h * HEAD_DIM + (lane & 3) * 2;
#pragma unroll
    for (int j = 0; j < 16; j++) {
        const size_t o0 = ((size_t)(b * SEQ + r0)) * D_MODEL + cbase + 8 * j;
        const size_t o1 = ((size_t)(b * SEQ + r0 + 8)) * D_MODEL + cbase + 8 * j;
        uint32_t hh, ll;
        split2(oacc[j][0] * li0, oacc[j][1] * li0, hh, ll);
        *(uint32_t*)&Ch[o0] = hh; *(uint32_t*)&Cl[o0] = ll;
        split2(oacc[j][2] * li1, oacc[j][3] * li1, hh, ll);
        *(uint32_t*)&Ch[o1] = hh; *(uint32_t*)&Cl[o1] = ll;
    }
}

// ============================================================================
// launch
// ============================================================================
extern "C" void kernel_launch(void* const* d_in, const int* in_sizes, int n_in,
                              void* d_out, int out_size)
{
    const float* x  = (const float*)d_in[0];
    const float* wq = (const float*)d_in[1];
    const float* wk = (const float*)d_in[2];
    const float* wv = (const float*)d_in[3];
    const float* wo = (const float*)d_in[4];
    float* out = (float*)d_out;

    __nv_bfloat16 *xh, *xl, *wh, *wl, *Qh, *Ql, *Kh, *Kl, *Vh, *Vl, *Ch, *Cl;
    cudaGetSymbolAddress((void**)&xh, g_xh);
    cudaGetSymbolAddress((void**)&xl, g_xl);
    cudaGetSymbolAddress((void**)&wh, g_wh);
    cudaGetSymbolAddress((void**)&wl, g_wl);
    cudaGetSymbolAddress((void**)&Qh, g_Qh);
    cudaGetSymbolAddress((void**)&Ql, g_Ql);
    cudaGetSymbolAddress((void**)&Kh, g_Kh);
    cudaGetSymbolAddress((void**)&Kl, g_Kl);
    cudaGetSymbolAddress((void**)&Vh, g_Vh);
    cudaGetSymbolAddress((void**)&Vl, g_Vl);
    cudaGetSymbolAddress((void**)&Ch, g_Ch);
    cudaGetSymbolAddress((void**)&Cl, g_Cl);

    cudaFuncSetAttribute(gemm_mma_kernel<true>,
                         cudaFuncAttributeMaxDynamicSharedMemorySize, GEMM_SMEM);
    cudaFuncSetAttribute(gemm_mma_kernel<false>,
                         cudaFuncAttributeMaxDynamicSharedMemorySize, GEMM_SMEM);
    cudaFuncSetAttribute(flash_mma_kernel,
                         cudaFuncAttributeMaxDynamicSharedMemorySize, FLASH_SMEM);

    const int nx4 = M_TOTAL * D_MODEL / 4;
    const int nw4 = D_MODEL * D_MODEL / 4;
    dim3 gg(D_MODEL / 128, M_TOTAL / 128);   // (16, 32)

    split_kernel<<<(nx4 + 255) / 256, 256>>>((const float4*)x, (uint2*)xh, (uint2*)xl, nx4);

    split_kernel<<<(nw4 + 255) / 256, 256>>>((const float4*)wq, (uint2*)wh, (uint2*)wl, nw4);
    gemm_mma_kernel<true><<<gg, 256, GEMM_SMEM>>>(xh, xl, wh, wl, nullptr, Qh, Ql);
    split_kernel<<<(nw4 + 255) / 256, 256>>>((const float4*)wk, (uint2*)wh, (uint2*)wl, nw4);
    gemm_mma_kernel<true><<<gg, 256, GEMM_SMEM>>>(xh, xl, wh, wl, nullptr, Kh, Kl);
    split_kernel<<<(nw4 + 255) / 256, 256>>>((const float4*)wv, (uint2*)wh, (uint2*)wl, nw4);
    gemm_mma_kernel<true><<<gg, 256, GEMM_SMEM>>>(xh, xl, wh, wl, nullptr, Vh, Vl);

    flash_mma_kernel<<<dim3(SEQ / TQF, BATCH * NUM_HEADS), 256, FLASH_SMEM>>>(
        Qh, Ql, Kh, Kl, Vh, Vl, Ch, Cl);

    split_kernel<<<(nw4 + 255) / 256, 256>>>((const float4*)wo, (uint2*)wh, (uint2*)wl, nw4);
    gemm_mma_kernel<false><<<gg, 256, GEMM_SMEM>>>(Ch, Cl, wh, wl, out, nullptr, nullptr);
}

// round 6
// speedup vs baseline: 3.6090x; 1.7117x over previous
#include <cuda_runtime.h>
#include <cuda_bf16.h>
#include <cstdint>
#include <math.h>

#define D_MODEL   2048
#define NUM_HEADS 16
#define HEAD_DIM  128
#define BATCH     2
#define SEQ       2048
#define M_TOTAL   (BATCH * SEQ)   // 4096

// ---------------- scratch (static device globals: no allocation allowed) ----
__device__ __nv_bfloat16 g_xh[M_TOTAL * D_MODEL];
__device__ __nv_bfloat16 g_xl[M_TOTAL * D_MODEL];
__device__ __nv_bfloat16 g_wqh[D_MODEL * D_MODEL];
__device__ __nv_bfloat16 g_wql[D_MODEL * D_MODEL];
__device__ __nv_bfloat16 g_wkh[D_MODEL * D_MODEL];
__device__ __nv_bfloat16 g_wkl[D_MODEL * D_MODEL];
__device__ __nv_bfloat16 g_wvh[D_MODEL * D_MODEL];
__device__ __nv_bfloat16 g_wvl[D_MODEL * D_MODEL];
__device__ __nv_bfloat16 g_woh[D_MODEL * D_MODEL];
__device__ __nv_bfloat16 g_wol[D_MODEL * D_MODEL];
__device__ __nv_bfloat16 g_Qh[M_TOTAL * D_MODEL];
__device__ __nv_bfloat16 g_Ql[M_TOTAL * D_MODEL];
__device__ __nv_bfloat16 g_Kh[M_TOTAL * D_MODEL];
__device__ __nv_bfloat16 g_Kl[M_TOTAL * D_MODEL];
__device__ __nv_bfloat16 g_Vh[M_TOTAL * D_MODEL];
__device__ __nv_bfloat16 g_Vl[M_TOTAL * D_MODEL];
__device__ __nv_bfloat16 g_Ch[M_TOTAL * D_MODEL];
__device__ __nv_bfloat16 g_Cl[M_TOTAL * D_MODEL];

// ============================================================================
// helpers
// ============================================================================
__device__ __forceinline__ uint32_t smem_u32(const void* p) {
    uint32_t a;
    asm("{ .reg .u64 t; cvta.to.shared.u64 t, %1; cvt.u32.u64 %0, t; }"
        : "=r"(a) : "l"(p));
    return a;
}
#define SW128(o) ((o) ^ (((o) >> 3) & 0x70))

__device__ __forceinline__ void ldsm4(uint32_t* r, uint32_t addr) {
    asm volatile("ldmatrix.sync.aligned.m8n8.x4.shared.b16 {%0,%1,%2,%3}, [%4];"
                 : "=r"(r[0]), "=r"(r[1]), "=r"(r[2]), "=r"(r[3]) : "r"(addr));
}
__device__ __forceinline__ void ldsm4t(uint32_t* r, uint32_t addr) {
    asm volatile("ldmatrix.sync.aligned.m8n8.x4.trans.shared.b16 {%0,%1,%2,%3}, [%4];"
                 : "=r"(r[0]), "=r"(r[1]), "=r"(r[2]), "=r"(r[3]) : "r"(addr));
}
__device__ __forceinline__ void mma16816(float* d, const uint32_t* a,
                                         const uint32_t* b) {
    asm volatile(
        "mma.sync.aligned.m16n8k16.row.col.f32.bf16.bf16.f32 "
        "{%0,%1,%2,%3}, {%4,%5,%6,%7}, {%8,%9}, {%0,%1,%2,%3};"
        : "+f"(d[0]), "+f"(d[1]), "+f"(d[2]), "+f"(d[3])
        : "r"(a[0]), "r"(a[1]), "r"(a[2]), "r"(a[3]), "r"(b[0]), "r"(b[1]));
}
__device__ __forceinline__ void cpasync16(uint32_t dst, const void* src) {
    asm volatile("cp.async.cg.shared.global [%0], [%1], 16;"
                 :: "r"(dst), "l"(src) : "memory");
}
#define CP_COMMIT() asm volatile("cp.async.commit_group;" ::: "memory")
#define CP_WAIT1()  asm volatile("cp.async.wait_group 1;" ::: "memory")
#define CP_WAIT0()  asm volatile("cp.async.wait_group 0;" ::: "memory")

// fp32 pair -> bf16x2 hi + bf16x2 lo (residual)
__device__ __forceinline__ void split2(float a, float b, uint32_t& hi, uint32_t& lo) {
    __nv_bfloat162 h = __floats2bfloat162_rn(a, b);
    hi = *(uint32_t*)&h;
    float ra = a - __bfloat162float(h.x);
    float rb = b - __bfloat162float(h.y);
    __nv_bfloat162 l = __floats2bfloat162_rn(ra, rb);
    lo = *(uint32_t*)&l;
}

// fast 2^y on the FMA/ALU pipes (no MUFU). y <= ~0; -inf -> 0.
__device__ __forceinline__ float fexp2(float y) {
    y = fmaxf(y, -120.f);
    const float t = y + 12582912.f;          // 1.5*2^23: round(y) in mantissa
    const int   i = __float_as_int(t);
    const float f = y - (t - 12582912.f);    // f in [-0.5, 0.5]
    float p = 1.33335581e-3f;
    p = fmaf(p, f, 9.61812910e-3f);
    p = fmaf(p, f, 5.55041087e-2f);
    p = fmaf(p, f, 2.40226507e-1f);
    p = fmaf(p, f, 6.93147181e-1f);
    p = fmaf(p, f, 1.0f);
    return __int_as_float(__float_as_int(p) + (i << 23));
}

// ============================================================================
// split kernels: fp32 -> (bf16 hi, bf16 lo)
// ============================================================================
__global__ __launch_bounds__(256)
void split_kernel(const float4* __restrict__ src, uint2* __restrict__ hi,
                  uint2* __restrict__ lo, int n4)
{
    int i = blockIdx.x * blockDim.x + threadIdx.x;
    if (i >= n4) return;
    float4 x = src[i];
    uint2 ho, lv;
    split2(x.x, x.y, ho.x, lv.x);
    split2(x.z, x.w, ho.y, lv.y);
    hi[i] = ho;
    lo[i] = lv;
}

__global__ __launch_bounds__(256)
void splitw_kernel(const float4* __restrict__ wq, const float4* __restrict__ wk,
                   const float4* __restrict__ wv, const float4* __restrict__ wo,
                   uint2* qh, uint2* ql, uint2* kh, uint2* kl,
                   uint2* vh, uint2* vl, uint2* oh, uint2* ol, int n4)
{
    int i = blockIdx.x * blockDim.x + threadIdx.x;
    if (i >= n4) return;
    const float4* s; uint2 *h, *l;
    switch (blockIdx.y) {
        case 0:  s = wq; h = qh; l = ql; break;
        case 1:  s = wk; h = kh; l = kl; break;
        case 2:  s = wv; h = vh; l = vl; break;
        default: s = wo; h = oh; l = ol; break;
    }
    float4 x = s[i];
    uint2 ho, lv;
    split2(x.x, x.y, ho.x, lv.x);
    split2(x.z, x.w, ho.y, lv.y);
    h[i] = ho;
    l[i] = lv;
}

// ============================================================================
// Tensor-core GEMM (NT) body, 3-term bf16 compensation, cp.async 2-stage.
//   C[m,n] = sum_k A[m,k]*B[n,k] ~= Ah*Bh + Al*Bh + Ah*Bl   (fp32 accum)
// CTA 128x128, K chunk 64, 8 warps (warp 64x32).
// ============================================================================
#define TKF 64
#define NCHUNK (D_MODEL / TKF)     // 32
#define G_STAGE 65536
#define G_AH 0
#define G_AL 16384
#define G_BH 32768
#define G_BL 49152
#define GEMM_SMEM (2 * G_STAGE)    // 131072

template<bool SPLIT>
__device__ __forceinline__
void gemm_body(const __nv_bfloat16* __restrict__ Ah,
               const __nv_bfloat16* __restrict__ Al,
               const __nv_bfloat16* __restrict__ Bh,
               const __nv_bfloat16* __restrict__ Bl,
               float* __restrict__ C,
               __nv_bfloat16* __restrict__ Ch,
               __nv_bfloat16* __restrict__ Cl,
               char* smc)
{
    const uint32_t sb = smem_u32(smc);
    const int tid  = threadIdx.x;
    const int wid  = tid >> 5;
    const int lane = tid & 31;
    const int bN = blockIdx.x * 128;
    const int bM = blockIdx.y * 128;
    const int wm = (wid & 1) * 64;
    const int wn = (wid >> 1) * 32;

    const int a_row = wm + (lane & 15);
    const int a_kh  = (lane >> 4) * 8;
    const int b_jg  = (lane >> 4);
    const int b_kh  = ((lane >> 3) & 1) * 8;
    const int b_r8  = lane & 7;

    const __nv_bfloat16* srcs[4] = {
        Ah + (size_t)bM * D_MODEL, Al + (size_t)bM * D_MODEL,
        Bh + (size_t)bN * D_MODEL, Bl + (size_t)bN * D_MODEL };

    auto prefetch = [&](int c, int stage) {
        const int k0 = c * TKF;
        const uint32_t base = sb + stage * G_STAGE;
#pragma unroll
        for (int t = 0; t < 4; t++) {
            const __nv_bfloat16* s = srcs[t] + k0;
#pragma unroll
            for (int it = 0; it < 4; it++) {
                const int vec = tid + it * 256;
                const int r = vec >> 3, v = vec & 7;
                cpasync16(base + t * 16384 + SW128((uint32_t)(r * 128 + v * 16)),
                          s + (size_t)r * D_MODEL + v * 8);
            }
        }
    };

    float acc[4][4][4] = {};

    prefetch(0, 0);
    CP_COMMIT();

    for (int c = 0; c < NCHUNK; c++) {
        if (c + 1 < NCHUNK) { prefetch(c + 1, (c + 1) & 1); CP_COMMIT(); CP_WAIT1(); }
        else                { CP_WAIT0(); }
        __syncthreads();

        const uint32_t st = sb + (c & 1) * G_STAGE;
#pragma unroll
        for (int ks = 0; ks < 4; ks++) {
            const int k16 = ks * 16;
            uint32_t ahf[4][4], alf[4][4], bf[4][2];
#pragma unroll
            for (int i = 0; i < 4; i++)
                ldsm4(ahf[i], st + G_AH +
                      SW128((uint32_t)((a_row + i * 16) * 128 + (k16 + a_kh) * 2)));
#pragma unroll
            for (int p = 0; p < 2; p++) {
                uint32_t r[4];
                const int jr = wn + (p * 2 + b_jg) * 8 + b_r8;
                ldsm4(r, st + G_BH + SW128((uint32_t)(jr * 128 + (k16 + b_kh) * 2)));
                bf[p * 2 + 0][0] = r[0]; bf[p * 2 + 0][1] = r[1];
                bf[p * 2 + 1][0] = r[2]; bf[p * 2 + 1][1] = r[3];
            }
#pragma unroll
            for (int i = 0; i < 4; i++)
#pragma unroll
                for (int j = 0; j < 4; j++)
                    mma16816(acc[i][j], ahf[i], bf[j]);
#pragma unroll
            for (int i = 0; i < 4; i++)
                ldsm4(alf[i], st + G_AL +
                      SW128((uint32_t)((a_row + i * 16) * 128 + (k16 + a_kh) * 2)));
#pragma unroll
            for (int i = 0; i < 4; i++)
#pragma unroll
                for (int j = 0; j < 4; j++)
                    mma16816(acc[i][j], alf[i], bf[j]);
#pragma unroll
            for (int p = 0; p < 2; p++) {
                uint32_t r[4];
                const int jr = wn + (p * 2 + b_jg) * 8 + b_r8;
                ldsm4(r, st + G_BL + SW128((uint32_t)(jr * 128 + (k16 + b_kh) * 2)));
                bf[p * 2 + 0][0] = r[0]; bf[p * 2 + 0][1] = r[1];
                bf[p * 2 + 1][0] = r[2]; bf[p * 2 + 1][1] = r[3];
            }
#pragma unroll
            for (int i = 0; i < 4; i++)
#pragma unroll
                for (int j = 0; j < 4; j++)
                    mma16816(acc[i][j], ahf[i], bf[j]);
        }
        __syncthreads();
    }

    const int er = bM + wm + (lane >> 2);
    const int ec = bN + wn + (lane & 3) * 2;
#pragma unroll
    for (int i = 0; i < 4; i++)
#pragma unroll
        for (int j = 0; j < 4; j++) {
            const size_t o0 = (size_t)(er + i * 16) * D_MODEL + ec + j * 8;
            const size_t o1 = (size_t)(er + i * 16 + 8) * D_MODEL + ec + j * 8;
            if (SPLIT) {
                uint32_t h, l;
                split2(acc[i][j][0], acc[i][j][1], h, l);
                *(uint32_t*)&Ch[o0] = h; *(uint32_t*)&Cl[o0] = l;
                split2(acc[i][j][2], acc[i][j][3], h, l);
                *(uint32_t*)&Ch[o1] = h; *(uint32_t*)&Cl[o1] = l;
            } else {
                *(float2*)&C[o0] = make_float2(acc[i][j][0], acc[i][j][1]);
                *(float2*)&C[o1] = make_float2(acc[i][j][2], acc[i][j][3]);
            }
        }
}

// fused Q/K/V projections: blockIdx.z selects weight + output
__global__ __launch_bounds__(256, 1)
void gemm_qkv_kernel(const __nv_bfloat16* __restrict__ xh,
                     const __nv_bfloat16* __restrict__ xl,
                     const __nv_bfloat16* wqh, const __nv_bfloat16* wql,
                     const __nv_bfloat16* wkh, const __nv_bfloat16* wkl,
                     const __nv_bfloat16* wvh, const __nv_bfloat16* wvl,
                     __nv_bfloat16* Qh, __nv_bfloat16* Ql,
                     __nv_bfloat16* Kh, __nv_bfloat16* Kl,
                     __nv_bfloat16* Vh, __nv_bfloat16* Vl)
{
    extern __shared__ char smc[];
    const __nv_bfloat16 *Bh, *Bl;
    __nv_bfloat16 *Ch, *Cl;
    if (blockIdx.z == 0)      { Bh = wqh; Bl = wql; Ch = Qh; Cl = Ql; }
    else if (blockIdx.z == 1) { Bh = wkh; Bl = wkl; Ch = Kh; Cl = Kl; }
    else                      { Bh = wvh; Bl = wvl; Ch = Vh; Cl = Vl; }
    gemm_body<true>(xh, xl, Bh, Bl, nullptr, Ch, Cl, smc);
}

__global__ __launch_bounds__(256, 1)
void gemm_o_kernel(const __nv_bfloat16* __restrict__ Ah,
                   const __nv_bfloat16* __restrict__ Al,
                   const __nv_bfloat16* __restrict__ Bh,
                   const __nv_bfloat16* __restrict__ Bl,
                   float* __restrict__ C)
{
    extern __shared__ char smc[];
    gemm_body<false>(Ah, Al, Bh, Bl, C, nullptr, nullptr, smc);
}

// ============================================================================
// Causal flash attention, mma.sync bf16 3-term, base-2 softmax on FMA pipe,
// cp.async double-buffered K/V. CTA = 128 q-rows x full head, K tile 64.
// Smem: Q 64KB + 2 KV stages x 64KB = 192KB. 8 warps (warp = 16 q-rows).
// ============================================================================
#define TQF 128
#define TKN 64
#define FQ_BASE  0
#define FKV_BASE 65536
#define KV_STAGE 65536
#define FLASH_SMEM (FKV_BASE + 2 * KV_STAGE)   // 196608

__global__ __launch_bounds__(256, 1)
void flash_mma_kernel(const __nv_bfloat16* __restrict__ Qh,
                      const __nv_bfloat16* __restrict__ Ql,
                      const __nv_bfloat16* __restrict__ Kh,
                      const __nv_bfloat16* __restrict__ Kl,
                      const __nv_bfloat16* __restrict__ Vh,
                      const __nv_bfloat16* __restrict__ Vl,
                      __nv_bfloat16* __restrict__ Ch,
                      __nv_bfloat16* __restrict__ Cl)
{
    extern __shared__ char smf[];
    const uint32_t sb = smem_u32(smf);
    const int tid  = threadIdx.x;
    const int wid  = tid >> 5;
    const int lane = tid & 31;

    const int qt = (int)(gridDim.x - 1) - (int)blockIdx.x;  // heavy CTAs first
    const int bh = blockIdx.y;
    const int b  = bh >> 4;
    const int h  = bh & 15;
    const int q0 = qt * TQF;
    // base-2 domain: scores scaled by 1/sqrt(128) * log2(e)
    const float C2 = 0.08838834764831845f * 1.4426950408889634f;

    const size_t qbase  = ((size_t)(b * SEQ + q0)) * D_MODEL + h * HEAD_DIM;
    const size_t kvbase = ((size_t)(b * SEQ)) * D_MODEL + h * HEAD_DIM;

    const int nkt = 2 * qt + 2;

    auto prefetch_kv = [&](int kt, int stage) {
        const int k0 = kt * TKN;
        const uint32_t st = sb + FKV_BASE + stage * KV_STAGE;
        for (int i = tid; i < TKN * 16; i += 256) {
            const int r = i >> 4, v = i & 15;
            const size_t g = kvbase + (size_t)(k0 + r) * D_MODEL + v * 8;
            const uint32_t so = (uint32_t)((v >> 3) * 8192)
                              + SW128((uint32_t)(r * 128 + (v & 7) * 16));
            cpasync16(st + so,         Kh + g);
            cpasync16(st + 16384 + so, Kl + g);
            cpasync16(st + 32768 + so, Vh + g);
            cpasync16(st + 49152 + so, Vl + g);
        }
    };

    // ---- load Q tile (hi+lo), subtiles split at d=64 ----
    for (int i = tid; i < TQF * 16; i += 256) {
        const int r = i >> 4, v = i & 15;
        const uint32_t so = (uint32_t)((v >> 3) * 16384)
                          + SW128((uint32_t)(r * 128 + (v & 7) * 16));
        *(uint4*)(smf + FQ_BASE + so) =
            *(const uint4*)(Qh + qbase + (size_t)r * D_MODEL + v * 8);
        *(uint4*)(smf + FQ_BASE + 32768 + so) =
            *(const uint4*)(Ql + qbase + (size_t)r * D_MODEL + v * 8);
    }
    prefetch_kv(0, 0);
    CP_COMMIT();

    const int wm = wid * 16;
    const int a_row = wm + (lane & 15);
    const int a_kh  = (lane >> 4) * 8;

    float oacc[16][4] = {};
    float m0 = -INFINITY, m1 = -INFINITY, l0 = 0.f, l1 = 0.f;

    for (int kt = 0; kt < nkt; kt++) {
        const int k0 = kt * TKN;
        if (kt + 1 < nkt) { prefetch_kv(kt + 1, (kt + 1) & 1); CP_COMMIT(); CP_WAIT1(); }
        else              { CP_WAIT0(); }
        __syncthreads();
        const uint32_t st = sb + FKV_BASE + (kt & 1) * KV_STAGE;

        // ---- S = Q K^T (3-term) ----
        float sacc[8][4] = {};
#pragma unroll
        for (int s = 0; s < 8; s++) {
            const int sub = s >> 2, kb = (s & 3) * 16;
            const uint32_t qoff = (uint32_t)(sub * 16384) +
                SW128((uint32_t)(a_row * 128 + (kb + a_kh) * 2));
            uint32_t qhf[4], qlf[4], kf[8][2];
            ldsm4(qhf, sb + FQ_BASE + qoff);
            ldsm4(qlf, sb + FQ_BASE + 32768 + qoff);
#pragma unroll
            for (int p = 0; p < 4; p++) {
                uint32_t r[4];
                const int jr = (p * 2 + (lane >> 4)) * 8 + (lane & 7);
                ldsm4(r, st + sub * 8192 +
                      SW128((uint32_t)(jr * 128 + (kb + ((lane >> 3) & 1) * 8) * 2)));
                kf[p * 2 + 0][0] = r[0]; kf[p * 2 + 0][1] = r[1];
                kf[p * 2 + 1][0] = r[2]; kf[p * 2 + 1][1] = r[3];
            }
#pragma unroll
            for (int j = 0; j < 8; j++) mma16816(sacc[j], qhf, kf[j]);
#pragma unroll
            for (int j = 0; j < 8; j++) mma16816(sacc[j], qlf, kf[j]);
#pragma unroll
            for (int p = 0; p < 4; p++) {
                uint32_t r[4];
                const int jr = (p * 2 + (lane >> 4)) * 8 + (lane & 7);
                ldsm4(r, st + 16384 + sub * 8192 +
                      SW128((uint32_t)(jr * 128 + (kb + ((lane >> 3) & 1) * 8) * 2)));
                kf[p * 2 + 0][0] = r[0]; kf[p * 2 + 0][1] = r[1];
                kf[p * 2 + 1][0] = r[2]; kf[p * 2 + 1][1] = r[3];
            }
#pragma unroll
            for (int j = 0; j < 8; j++) mma16816(sacc[j], qhf, kf[j]);
        }

        // ---- scale (base-2) + causal mask ----
        const bool needmask = (k0 + TKN - 1) > (q0 + wm);
        const int rl = lane >> 2, cl = (lane & 3) * 2;
#pragma unroll
        for (int j = 0; j < 8; j++)
#pragma unroll
            for (int e = 0; e < 4; e++) {
                float v = sacc[j][e] * C2;
                if (needmask) {
                    const int colg = k0 + 8 * j + cl + (e & 1);
                    const int rowg = q0 + wm + rl + (e >> 1) * 8;
                    if (colg > rowg) v = -INFINITY;
                }
                sacc[j][e] = v;
            }

        // ---- online softmax (all exp2 on FMA pipe) ----
        float mt0 = -INFINITY, mt1 = -INFINITY;
#pragma unroll
        for (int j = 0; j < 8; j++) {
            mt0 = fmaxf(mt0, fmaxf(sacc[j][0], sacc[j][1]));
            mt1 = fmaxf(mt1, fmaxf(sacc[j][2], sacc[j][3]));
        }
        mt0 = fmaxf(mt0, __shfl_xor_sync(0xFFFFFFFFu, mt0, 1));
        mt0 = fmaxf(mt0, __shfl_xor_sync(0xFFFFFFFFu, mt0, 2));
        mt1 = fmaxf(mt1, __shfl_xor_sync(0xFFFFFFFFu, mt1, 1));
        mt1 = fmaxf(mt1, __shfl_xor_sync(0xFFFFFFFFu, mt1, 2));
        const float mn0 = fmaxf(m0, mt0), mn1 = fmaxf(m1, mt1);
        const float al0 = fexp2(m0 - mn0), al1 = fexp2(m1 - mn1);
        float s0 = 0.f, s1 = 0.f;
#pragma unroll
        for (int j = 0; j < 8; j++) {
            sacc[j][0] = fexp2(sacc[j][0] - mn0); s0 += sacc[j][0];
            sacc[j][1] = fexp2(sacc[j][1] - mn0); s0 += sacc[j][1];
            sacc[j][2] = fexp2(sacc[j][2] - mn1); s1 += sacc[j][2];
            sacc[j][3] = fexp2(sacc[j][3] - mn1); s1 += sacc[j][3];
        }
        s0 += __shfl_xor_sync(0xFFFFFFFFu, s0, 1);
        s0 += __shfl_xor_sync(0xFFFFFFFFu, s0, 2);
        s1 += __shfl_xor_sync(0xFFFFFFFFu, s1, 1);
        s1 += __shfl_xor_sync(0xFFFFFFFFu, s1, 2);
        l0 = l0 * al0 + s0;
        l1 = l1 * al1 + s1;
        m0 = mn0; m1 = mn1;
#pragma unroll
        for (int j = 0; j < 16; j++) {
            oacc[j][0] *= al0; oacc[j][1] *= al0;
            oacc[j][2] *= al1; oacc[j][3] *= al1;
        }

        // ---- O += P V (3-term), V^T frags via ldmatrix.trans ----
#pragma unroll
        for (int s2 = 0; s2 < 4; s2++) {
            uint32_t ph[4], pl[4];
            split2(sacc[2 * s2][0],     sacc[2 * s2][1],     ph[0], pl[0]);
            split2(sacc[2 * s2][2],     sacc[2 * s2][3],     ph[1], pl[1]);
            split2(sacc[2 * s2 + 1][0], sacc[2 * s2 + 1][1], ph[2], pl[2]);
            split2(sacc[2 * s2 + 1][2], sacc[2 * s2 + 1][3], ph[3], pl[3]);
            const int vrow = 16 * s2 + ((lane >> 3) & 1) * 8 + (lane & 7);
#pragma unroll
            for (int p = 0; p < 8; p++) {
                const uint32_t voff = (uint32_t)((p >> 2) * 8192) +
                    SW128((uint32_t)(vrow * 128 + 32 * (p & 3) + (lane >> 4) * 16));
                uint32_t r[4];
                ldsm4t(r, st + 32768 + voff);
                uint32_t b0[2] = { r[0], r[1] }, b1[2] = { r[2], r[3] };
                mma16816(oacc[2 * p],     ph, b0);
                mma16816(oacc[2 * p + 1], ph, b1);
                mma16816(oacc[2 * p],     pl, b0);
                mma16816(oacc[2 * p + 1], pl, b1);
                ldsm4t(r, st + 49152 + voff);
                uint32_t c0[2] = { r[0], r[1] }, c1[2] = { r[2], r[3] };
                mma16816(oacc[2 * p],     ph, c0);
                mma16816(oacc[2 * p + 1], ph, c1);
            }
        }
        __syncthreads();   // all warps done reading this stage before overwrite
    }

    // ---- epilogue: normalize, split to bf16 hi/lo, store CTX ----
    const float li0 = 1.f / l0, li1 = 1.f / l1;
    const int r0 = q0 + wm + (lane >> 2);
    const int cbase = h * HEAD_DIM + (lane & 3) * 2;
#pragma unroll
    for (int j = 0; j < 16; j++) {
        const size_t o0 = ((size_t)(b * SEQ + r0)) * D_MODEL + cbase + 8 * j;
        const size_t o1 = ((size_t)(b * SEQ + r0 + 8)) * D_MODEL + cbase + 8 * j;
        uint32_t hh, ll;
        split2(oacc[j][0] * li0, oacc[j][1] * li0, hh, ll);
        *(uint32_t*)&Ch[o0] = hh; *(uint32_t*)&Cl[o0] = ll;
        split2(oacc[j][2] * li1, oacc[j][3] * li1, hh, ll);
        *(uint32_t*)&Ch[o1] = hh; *(uint32_t*)&Cl[o1] = ll;
    }
}

// ============================================================================
// launch
// ============================================================================
extern "C" void kernel_launch(void* const* d_in, const int* in_sizes, int n_in,
                              void* d_out, int out_size)
{
    const float* x  = (const float*)d_in[0];
    const float* wq = (const float*)d_in[1];
    const float* wk = (const float*)d_in[2];
    const float* wv = (const float*)d_in[3];
    const float* wo = (const float*)d_in[4];
    float* out = (float*)d_out;

    __nv_bfloat16 *xh, *xl, *Qh, *Ql, *Kh, *Kl, *Vh, *Vl, *Ch, *Cl;
    __nv_bfloat16 *wqh, *wql, *wkh, *wkl, *wvh, *wvl, *woh, *wol;
    cudaGetSymbolAddress((void**)&xh, g_xh);
    cudaGetSymbolAddress((void**)&xl, g_xl);
    cudaGetSymbolAddress((void**)&wqh, g_wqh);
    cudaGetSymbolAddress((void**)&wql, g_wql);
    cudaGetSymbolAddress((void**)&wkh, g_wkh);
    cudaGetSymbolAddress((void**)&wkl, g_wkl);
    cudaGetSymbolAddress((void**)&wvh, g_wvh);
    cudaGetSymbolAddress((void**)&wvl, g_wvl);
    cudaGetSymbolAddress((void**)&woh, g_woh);
    cudaGetSymbolAddress((void**)&wol, g_wol);
    cudaGetSymbolAddress((void**)&Qh, g_Qh);
    cudaGetSymbolAddress((void**)&Ql, g_Ql);
    cudaGetSymbolAddress((void**)&Kh, g_Kh);
    cudaGetSymbolAddress((void**)&Kl, g_Kl);
    cudaGetSymbolAddress((void**)&Vh, g_Vh);
    cudaGetSymbolAddress((void**)&Vl, g_Vl);
    cudaGetSymbolAddress((void**)&Ch, g_Ch);
    cudaGetSymbolAddress((void**)&Cl, g_Cl);

    cudaFuncSetAttribute(gemm_qkv_kernel,
                         cudaFuncAttributeMaxDynamicSharedMemorySize, GEMM_SMEM);
    cudaFuncSetAttribute(gemm_o_kernel,
                         cudaFuncAttributeMaxDynamicSharedMemorySize, GEMM_SMEM);
    cudaFuncSetAttribute(flash_mma_kernel,
                         cudaFuncAttributeMaxDynamicSharedMemorySize, FLASH_SMEM);

    const int nx4 = M_TOTAL * D_MODEL / 4;
    const int nw4 = D_MODEL * D_MODEL / 4;

    split_kernel<<<(nx4 + 255) / 256, 256>>>((const float4*)x, (uint2*)xh, (uint2*)xl, nx4);
    splitw_kernel<<<dim3((nw4 + 255) / 256, 4), 256>>>(
        (const float4*)wq, (const float4*)wk, (const float4*)wv, (const float4*)wo,
        (uint2*)wqh, (uint2*)wql, (uint2*)wkh, (uint2*)wkl,
        (uint2*)wvh, (uint2*)wvl, (uint2*)woh, (uint2*)wol, nw4);

    gemm_qkv_kernel<<<dim3(D_MODEL / 128, M_TOTAL / 128, 3), 256, GEMM_SMEM>>>(
        xh, xl, wqh, wql, wkh, wkl, wvh, wvl, Qh, Ql, Kh, Kl, Vh, Vl);

    flash_mma_kernel<<<dim3(SEQ / TQF, BATCH * NUM_HEADS), 256, FLASH_SMEM>>>(
        Qh, Ql, Kh, Kl, Vh, Vl, Ch, Cl);

    gemm_o_kernel<<<dim3(D_MODEL / 128, M_TOTAL / 128), 256, GEMM_SMEM>>>(
        Ch, Cl, woh, wol, out);
}

// round 7
// speedup vs baseline: 4.9886x; 1.3823x over previous
#include <cuda_runtime.h>
#include <cuda_fp16.h>
#include <cstdint>
#include <math.h>

#define D_MODEL   2048
#define NUM_HEADS 16
#define HEAD_DIM  128
#define BATCH     2
#define SEQ       2048
#define M_TOTAL   (BATCH * SEQ)   // 4096

// ---------------- scratch (static device globals: no allocation allowed) ----
__device__ __half g_xh[M_TOTAL * D_MODEL];
__device__ __half g_xl[M_TOTAL * D_MODEL];
__device__ __half g_wqh[D_MODEL * D_MODEL];
__device__ __half g_wkh[D_MODEL * D_MODEL];
__device__ __half g_wvh[D_MODEL * D_MODEL];
__device__ __half g_woh[D_MODEL * D_MODEL];
__device__ __half g_Qh[M_TOTAL * D_MODEL];
__device__ __half g_Ql[M_TOTAL * D_MODEL];
__device__ __half g_Kh[M_TOTAL * D_MODEL];
__device__ __half g_Vh[M_TOTAL * D_MODEL];
__device__ __half g_Ch[M_TOTAL * D_MODEL];
__device__ __half g_Cl[M_TOTAL * D_MODEL];

// ============================================================================
// helpers
// ============================================================================
__device__ __forceinline__ uint32_t smem_u32(const void* p) {
    uint32_t a;
    asm("{ .reg .u64 t; cvta.to.shared.u64 t, %1; cvt.u32.u64 %0, t; }"
        : "=r"(a) : "l"(p));
    return a;
}
#define SW128(o) ((o) ^ (((o) >> 3) & 0x70))

__device__ __forceinline__ void ldsm4(uint32_t* r, uint32_t addr) {
    asm volatile("ldmatrix.sync.aligned.m8n8.x4.shared.b16 {%0,%1,%2,%3}, [%4];"
                 : "=r"(r[0]), "=r"(r[1]), "=r"(r[2]), "=r"(r[3]) : "r"(addr));
}
__device__ __forceinline__ void ldsm4t(uint32_t* r, uint32_t addr) {
    asm volatile("ldmatrix.sync.aligned.m8n8.x4.trans.shared.b16 {%0,%1,%2,%3}, [%4];"
                 : "=r"(r[0]), "=r"(r[1]), "=r"(r[2]), "=r"(r[3]) : "r"(addr));
}
__device__ __forceinline__ void mma16816(float* d, const uint32_t* a,
                                         const uint32_t* b) {
    asm volatile(
        "mma.sync.aligned.m16n8k16.row.col.f32.f16.f16.f32 "
        "{%0,%1,%2,%3}, {%4,%5,%6,%7}, {%8,%9}, {%0,%1,%2,%3};"
        : "+f"(d[0]), "+f"(d[1]), "+f"(d[2]), "+f"(d[3])
        : "r"(a[0]), "r"(a[1]), "r"(a[2]), "r"(a[3]), "r"(b[0]), "r"(b[1]));
}
__device__ __forceinline__ void cpasync16(uint32_t dst, const void* src) {
    asm volatile("cp.async.cg.shared.global [%0], [%1], 16;"
                 :: "r"(dst), "l"(src) : "memory");
}
#define CP_COMMIT() asm volatile("cp.async.commit_group;" ::: "memory")
#define CP_WAIT2()  asm volatile("cp.async.wait_group 2;" ::: "memory")
#define CP_WAIT1()  asm volatile("cp.async.wait_group 1;" ::: "memory")
#define CP_WAIT0()  asm volatile("cp.async.wait_group 0;" ::: "memory")

// fp32 pair -> fp16x2 hi + fp16x2 lo (residual)
__device__ __forceinline__ void split2h(float a, float b, uint32_t& hi, uint32_t& lo) {
    __half2 h = __floats2half2_rn(a, b);
    hi = *(uint32_t*)&h;
    float ra = a - __half2float(h.x);
    float rb = b - __half2float(h.y);
    __half2 l = __floats2half2_rn(ra, rb);
    lo = *(uint32_t*)&l;
}
__device__ __forceinline__ uint32_t pack2h(float a, float b) {
    __half2 h = __floats2half2_rn(a, b);
    return *(uint32_t*)&h;
}

// fast 2^y on the FMA/ALU pipes (no MUFU). y <= ~0; -inf -> 0.
__device__ __forceinline__ float fexp2(float y) {
    y = fmaxf(y, -120.f);
    const float t = y + 12582912.f;          // 1.5*2^23: round(y) in mantissa
    const int   i = __float_as_int(t);
    const float f = y - (t - 12582912.f);    // f in [-0.5, 0.5]
    float p = 1.33335581e-3f;
    p = fmaf(p, f, 9.61812910e-3f);
    p = fmaf(p, f, 5.55041087e-2f);
    p = fmaf(p, f, 2.40226507e-1f);
    p = fmaf(p, f, 6.93147181e-1f);
    p = fmaf(p, f, 1.0f);
    return __int_as_float(__float_as_int(p) + (i << 23));
}

// ============================================================================
// split kernels
// ============================================================================
__global__ __launch_bounds__(256)
void split_kernel(const float4* __restrict__ src, uint2* __restrict__ hi,
                  uint2* __restrict__ lo, int n4)
{
    int i = blockIdx.x * blockDim.x + threadIdx.x;
    if (i >= n4) return;
    float4 x = src[i];
    uint2 ho, lv;
    split2h(x.x, x.y, ho.x, lv.x);
    split2h(x.z, x.w, ho.y, lv.y);
    hi[i] = ho;
    lo[i] = lv;
}

// weights: round to fp16 only (no residual needed in 2-term scheme)
__global__ __launch_bounds__(256)
void roundw_kernel(const float4* __restrict__ wq, const float4* __restrict__ wk,
                   const float4* __restrict__ wv, const float4* __restrict__ wo,
                   uint2* qh, uint2* kh, uint2* vh, uint2* oh, int n4)
{
    int i = blockIdx.x * blockDim.x + threadIdx.x;
    if (i >= n4) return;
    const float4* s; uint2* h;
    switch (blockIdx.y) {
        case 0:  s = wq; h = qh; break;
        case 1:  s = wk; h = kh; break;
        case 2:  s = wv; h = vh; break;
        default: s = wo; h = oh; break;
    }
    float4 x = s[i];
    uint2 ho;
    ho.x = pack2h(x.x, x.y);
    ho.y = pack2h(x.z, x.w);
    h[i] = ho;
}

// ============================================================================
// Tensor-core GEMM (NT) body, fp16 2-term compensation, cp.async 3-stage.
//   C[m,n] = sum_k A[m,k]*B[n,k] ~= Ah*Bh + Al*Bh   (fp32 accum, B rounded)
// CTA 128x128, K chunk 64, 8 warps (warp 64x32).
// MODE: 0 = fp32 C, 1 = split hi/lo fp16, 2 = rounded fp16 only
// ============================================================================
#define TKF 64
#define NCHUNK (D_MODEL / TKF)     // 32
#define G_STAGE 49152
#define G_AH 0
#define G_AL 16384
#define G_BH 32768
#define GEMM_SMEM (3 * G_STAGE)    // 147456

template<int MODE>
__device__ __forceinline__
void gemm_body(const __half* __restrict__ Ah,
               const __half* __restrict__ Al,
               const __half* __restrict__ Bh,
               float* __restrict__ C,
               __half* __restrict__ Ch,
               __half* __restrict__ Cl,
               char* smc)
{
    const uint32_t sb = smem_u32(smc);
    const int tid  = threadIdx.x;
    const int wid  = tid >> 5;
    const int lane = tid & 31;
    const int bN = blockIdx.x * 128;
    const int bM = blockIdx.y * 128;
    const int wm = (wid & 1) * 64;
    const int wn = (wid >> 1) * 32;

    const int a_row = wm + (lane & 15);
    const int a_kh  = (lane >> 4) * 8;
    const int b_jg  = (lane >> 4);
    const int b_kh  = ((lane >> 3) & 1) * 8;
    const int b_r8  = lane & 7;

    const __half* srcs[3] = {
        Ah + (size_t)bM * D_MODEL, Al + (size_t)bM * D_MODEL,
        Bh + (size_t)bN * D_MODEL };

    auto prefetch = [&](int c, int stage) {
        const int k0 = c * TKF;
        const uint32_t base = sb + stage * G_STAGE;
#pragma unroll
        for (int t = 0; t < 3; t++) {
            const __half* s = srcs[t] + k0;
#pragma unroll
            for (int it = 0; it < 4; it++) {
                const int vec = tid + it * 256;
                const int r = vec >> 3, v = vec & 7;
                cpasync16(base + t * 16384 + SW128((uint32_t)(r * 128 + v * 16)),
                          s + (size_t)r * D_MODEL + v * 8);
            }
        }
    };

    float acc[4][4][4] = {};

    prefetch(0, 0); CP_COMMIT();
    prefetch(1, 1); CP_COMMIT();

    for (int c = 0; c < NCHUNK; c++) {
        if (c + 2 < NCHUNK)      { prefetch(c + 2, (c + 2) % 3); CP_COMMIT(); CP_WAIT2(); }
        else if (c + 1 < NCHUNK) { CP_WAIT1(); }
        else                     { CP_WAIT0(); }
        __syncthreads();

        const uint32_t st = sb + (c % 3) * G_STAGE;
#pragma unroll
        for (int ks = 0; ks < 4; ks++) {
            const int k16 = ks * 16;
            uint32_t ahf[4][4], alf[4][4], bf[4][2];
#pragma unroll
            for (int i = 0; i < 4; i++)
                ldsm4(ahf[i], st + G_AH +
                      SW128((uint32_t)((a_row + i * 16) * 128 + (k16 + a_kh) * 2)));
#pragma unroll
            for (int p = 0; p < 2; p++) {
                uint32_t r[4];
                const int jr = wn + (p * 2 + b_jg) * 8 + b_r8;
                ldsm4(r, st + G_BH + SW128((uint32_t)(jr * 128 + (k16 + b_kh) * 2)));
                bf[p * 2 + 0][0] = r[0]; bf[p * 2 + 0][1] = r[1];
                bf[p * 2 + 1][0] = r[2]; bf[p * 2 + 1][1] = r[3];
            }
#pragma unroll
            for (int i = 0; i < 4; i++)
#pragma unroll
                for (int j = 0; j < 4; j++)
                    mma16816(acc[i][j], ahf[i], bf[j]);
#pragma unroll
            for (int i = 0; i < 4; i++)
                ldsm4(alf[i], st + G_AL +
                      SW128((uint32_t)((a_row + i * 16) * 128 + (k16 + a_kh) * 2)));
#pragma unroll
            for (int i = 0; i < 4; i++)
#pragma unroll
                for (int j = 0; j < 4; j++)
                    mma16816(acc[i][j], alf[i], bf[j]);
        }
        __syncthreads();
    }

    const int er = bM + wm + (lane >> 2);
    const int ec = bN + wn + (lane & 3) * 2;
#pragma unroll
    for (int i = 0; i < 4; i++)
#pragma unroll
        for (int j = 0; j < 4; j++) {
            const size_t o0 = (size_t)(er + i * 16) * D_MODEL + ec + j * 8;
            const size_t o1 = (size_t)(er + i * 16 + 8) * D_MODEL + ec + j * 8;
            if (MODE == 0) {
                *(float2*)&C[o0] = make_float2(acc[i][j][0], acc[i][j][1]);
                *(float2*)&C[o1] = make_float2(acc[i][j][2], acc[i][j][3]);
            } else if (MODE == 1) {
                uint32_t h, l;
                split2h(acc[i][j][0], acc[i][j][1], h, l);
                *(uint32_t*)&Ch[o0] = h; *(uint32_t*)&Cl[o0] = l;
                split2h(acc[i][j][2], acc[i][j][3], h, l);
                *(uint32_t*)&Ch[o1] = h; *(uint32_t*)&Cl[o1] = l;
            } else {
                *(uint32_t*)&Ch[o0] = pack2h(acc[i][j][0], acc[i][j][1]);
                *(uint32_t*)&Ch[o1] = pack2h(acc[i][j][2], acc[i][j][3]);
            }
        }
}

// fused Q/K/V projections: blockIdx.z selects weight + output
__global__ __launch_bounds__(256, 1)
void gemm_qkv_kernel(const __half* __restrict__ xh, const __half* __restrict__ xl,
                     const __half* wqh, const __half* wkh, const __half* wvh,
                     __half* Qh, __half* Ql, __half* Kh, __half* Vh)
{
    extern __shared__ char smc[];
    if (blockIdx.z == 0)
        gemm_body<1>(xh, xl, wqh, nullptr, Qh, Ql, smc);   // Q: hi/lo split
    else if (blockIdx.z == 1)
        gemm_body<2>(xh, xl, wkh, nullptr, Kh, nullptr, smc);  // K: rounded
    else
        gemm_body<2>(xh, xl, wvh, nullptr, Vh, nullptr, smc);  // V: rounded
}

__global__ __launch_bounds__(256, 1)
void gemm_o_kernel(const __half* __restrict__ Ah, const __half* __restrict__ Al,
                   const __half* __restrict__ Bh, float* __restrict__ C)
{
    extern __shared__ char smc[];
    gemm_body<0>(Ah, Al, Bh, C, nullptr, nullptr, smc);
}

// ============================================================================
// Causal flash attention, mma.sync fp16 2-term, base-2 softmax on FMA pipe,
// cp.async double-buffered K/V. CTA = 128 q-rows x full head, K tile 64.
// Smem: Q(hi+lo) 64KB + 2 KV stages x 32KB = 128KB. 8 warps.
// ============================================================================
#define TQF 128
#define TKN 64
#define FQ_BASE  0
#define FKV_BASE 65536
#define KV_STAGE 32768
#define FLASH_SMEM (FKV_BASE + 2 * KV_STAGE)   // 131072

__global__ __launch_bounds__(256, 1)
void flash_mma_kernel(const __half* __restrict__ Qh, const __half* __restrict__ Ql,
                      const __half* __restrict__ Kh, const __half* __restrict__ Vh,
                      __half* __restrict__ Ch, __half* __restrict__ Cl)
{
    extern __shared__ char smf[];
    const uint32_t sb = smem_u32(smf);
    const int tid  = threadIdx.x;
    const int wid  = tid >> 5;
    const int lane = tid & 31;

    const int qt = (int)(gridDim.x - 1) - (int)blockIdx.x;  // heavy CTAs first
    const int bh = blockIdx.y;
    const int b  = bh >> 4;
    const int h  = bh & 15;
    const int q0 = qt * TQF;
    const float C2 = 0.08838834764831845f * 1.4426950408889634f; // scale*log2e

    const size_t qbase  = ((size_t)(b * SEQ + q0)) * D_MODEL + h * HEAD_DIM;
    const size_t kvbase = ((size_t)(b * SEQ)) * D_MODEL + h * HEAD_DIM;

    const int nkt = 2 * qt + 2;

    auto prefetch_kv = [&](int kt, int stage) {
        const int k0 = kt * TKN;
        const uint32_t st = sb + FKV_BASE + stage * KV_STAGE;
        for (int i = tid; i < TKN * 16; i += 256) {
            const int r = i >> 4, v = i & 15;
            const size_t g = kvbase + (size_t)(k0 + r) * D_MODEL + v * 8;
            const uint32_t so = (uint32_t)((v >> 3) * 8192)
                              + SW128((uint32_t)(r * 128 + (v & 7) * 16));
            cpasync16(st + so,         Kh + g);
            cpasync16(st + 16384 + so, Vh + g);
        }
    };

    // ---- load Q tile (hi+lo), subtiles split at d=64 ----
    for (int i = tid; i < TQF * 16; i += 256) {
        const int r = i >> 4, v = i & 15;
        const uint32_t so = (uint32_t)((v >> 3) * 16384)
                          + SW128((uint32_t)(r * 128 + (v & 7) * 16));
        *(uint4*)(smf + FQ_BASE + so) =
            *(const uint4*)(Qh + qbase + (size_t)r * D_MODEL + v * 8);
        *(uint4*)(smf + FQ_BASE + 32768 + so) =
            *(const uint4*)(Ql + qbase + (size_t)r * D_MODEL + v * 8);
    }
    prefetch_kv(0, 0);
    CP_COMMIT();

    const int wm = wid * 16;
    const int a_row = wm + (lane & 15);
    const int a_kh  = (lane >> 4) * 8;

    float oacc[16][4] = {};
    float m0 = -INFINITY, m1 = -INFINITY, l0 = 0.f, l1 = 0.f;

    for (int kt = 0; kt < nkt; kt++) {
        const int k0 = kt * TKN;
        if (kt + 1 < nkt) { prefetch_kv(kt + 1, (kt + 1) & 1); CP_COMMIT(); CP_WAIT1(); }
        else              { CP_WAIT0(); }
        __syncthreads();
        const uint32_t st = sb + FKV_BASE + (kt & 1) * KV_STAGE;

        // ---- S = Q K^T (2-term: Qh*Kh + Ql*Kh) ----
        float sacc[8][4] = {};
#pragma unroll
        for (int s = 0; s < 8; s++) {
            const int sub = s >> 2, kb = (s & 3) * 16;
            const uint32_t qoff = (uint32_t)(sub * 16384) +
                SW128((uint32_t)(a_row * 128 + (kb + a_kh) * 2));
            uint32_t qhf[4], qlf[4], kf[8][2];
            ldsm4(qhf, sb + FQ_BASE + qoff);
            ldsm4(qlf, sb + FQ_BASE + 32768 + qoff);
#pragma unroll
            for (int p = 0; p < 4; p++) {
                uint32_t r[4];
                const int jr = (p * 2 + (lane >> 4)) * 8 + (lane & 7);
                ldsm4(r, st + sub * 8192 +
                      SW128((uint32_t)(jr * 128 + (kb + ((lane >> 3) & 1) * 8) * 2)));
                kf[p * 2 + 0][0] = r[0]; kf[p * 2 + 0][1] = r[1];
                kf[p * 2 + 1][0] = r[2]; kf[p * 2 + 1][1] = r[3];
            }
#pragma unroll
            for (int j = 0; j < 8; j++) mma16816(sacc[j], qhf, kf[j]);
#pragma unroll
            for (int j = 0; j < 8; j++) mma16816(sacc[j], qlf, kf[j]);
        }

        // ---- scale (base-2) + causal mask ----
        const bool needmask = (k0 + TKN - 1) > (q0 + wm);
        const int rl = lane >> 2, cl = (lane & 3) * 2;
#pragma unroll
        for (int j = 0; j < 8; j++)
#pragma unroll
            for (int e = 0; e < 4; e++) {
                float v = sacc[j][e] * C2;
                if (needmask) {
                    const int colg = k0 + 8 * j + cl + (e & 1);
                    const int rowg = q0 + wm + rl + (e >> 1) * 8;
                    if (colg > rowg) v = -INFINITY;
                }
                sacc[j][e] = v;
            }

        // ---- online softmax (exp2 on FMA pipe) ----
        float mt0 = -INFINITY, mt1 = -INFINITY;
#pragma unroll
        for (int j = 0; j < 8; j++) {
            mt0 = fmaxf(mt0, fmaxf(sacc[j][0], sacc[j][1]));
            mt1 = fmaxf(mt1, fmaxf(sacc[j][2], sacc[j][3]));
        }
        mt0 = fmaxf(mt0, __shfl_xor_sync(0xFFFFFFFFu, mt0, 1));
        mt0 = fmaxf(mt0, __shfl_xor_sync(0xFFFFFFFFu, mt0, 2));
        mt1 = fmaxf(mt1, __shfl_xor_sync(0xFFFFFFFFu, mt1, 1));
        mt1 = fmaxf(mt1, __shfl_xor_sync(0xFFFFFFFFu, mt1, 2));
        const float mn0 = fmaxf(m0, mt0), mn1 = fmaxf(m1, mt1);
        const float al0 = fexp2(m0 - mn0), al1 = fexp2(m1 - mn1);
        float s0 = 0.f, s1 = 0.f;
#pragma unroll
        for (int j = 0; j < 8; j++) {
            sacc[j][0] = fexp2(sacc[j][0] - mn0); s0 += sacc[j][0];
            sacc[j][1] = fexp2(sacc[j][1] - mn0); s0 += sacc[j][1];
            sacc[j][2] = fexp2(sacc[j][2] - mn1); s1 += sacc[j][2];
            sacc[j][3] = fexp2(sacc[j][3] - mn1); s1 += sacc[j][3];
        }
        s0 += __shfl_xor_sync(0xFFFFFFFFu, s0, 1);
        s0 += __shfl_xor_sync(0xFFFFFFFFu, s0, 2);
        s1 += __shfl_xor_sync(0xFFFFFFFFu, s1, 1);
        s1 += __shfl_xor_sync(0xFFFFFFFFu, s1, 2);
        l0 = l0 * al0 + s0;
        l1 = l1 * al1 + s1;
        m0 = mn0; m1 = mn1;
#pragma unroll
        for (int j = 0; j < 16; j++) {
            oacc[j][0] *= al0; oacc[j][1] *= al0;
            oacc[j][2] *= al1; oacc[j][3] *= al1;
        }

        // ---- O += P V (2-term: Ph*Vh + Pl*Vh), V^T via ldmatrix.trans ----
#pragma unroll
        for (int s2 = 0; s2 < 4; s2++) {
            uint32_t ph[4], pl[4];
            split2h(sacc[2 * s2][0],     sacc[2 * s2][1],     ph[0], pl[0]);
            split2h(sacc[2 * s2][2],     sacc[2 * s2][3],     ph[1], pl[1]);
            split2h(sacc[2 * s2 + 1][0], sacc[2 * s2 + 1][1], ph[2], pl[2]);
            split2h(sacc[2 * s2 + 1][2], sacc[2 * s2 + 1][3], ph[3], pl[3]);
            const int vrow = 16 * s2 + ((lane >> 3) & 1) * 8 + (lane & 7);
#pragma unroll
            for (int p = 0; p < 8; p++) {
                const uint32_t voff = (uint32_t)((p >> 2) * 8192) +
                    SW128((uint32_t)(vrow * 128 + 32 * (p & 3) + (lane >> 4) * 16));
                uint32_t r[4];
                ldsm4t(r, st + 16384 + voff);
                uint32_t b0[2] = { r[0], r[1] }, b1[2] = { r[2], r[3] };
                mma16816(oacc[2 * p],     ph, b0);
                mma16816(oacc[2 * p + 1], ph, b1);
                mma16816(oacc[2 * p],     pl, b0);
                mma16816(oacc[2 * p + 1], pl, b1);
            }
        }
        __syncthreads();   // all warps done reading this stage before overwrite
    }

    // ---- epilogue: normalize, split to fp16 hi/lo, store CTX ----
    const float li0 = 1.f / l0, li1 = 1.f / l1;
    const int r0 = q0 + wm + (lane >> 2);
    const int cbase = h * HEAD_DIM + (lane & 3) * 2;
#pragma unroll
    for (int j = 0; j < 16; j++) {
        const size_t o0 = ((size_t)(b * SEQ + r0)) * D_MODEL + cbase + 8 * j;
        const size_t o1 = ((size_t)(b * SEQ + r0 + 8)) * D_MODEL + cbase + 8 * j;
        uint32_t hh, ll;
        split2h(oacc[j][0] * li0, oacc[j][1] * li0, hh, ll);
        *(uint32_t*)&Ch[o0] = hh; *(uint32_t*)&Cl[o0] = ll;
        split2h(oacc[j][2] * li1, oacc[j][3] * li1, hh, ll);
        *(uint32_t*)&Ch[o1] = hh; *(uint32_t*)&Cl[o1] = ll;
    }
}

// ============================================================================
// launch
// ============================================================================
extern "C" void kernel_launch(void* const* d_in, const int* in_sizes, int n_in,
                              void* d_out, int out_size)
{
    const float* x  = (const float*)d_in[0];
    const float* wq = (const float*)d_in[1];
    const float* wk = (const float*)d_in[2];
    const float* wv = (const float*)d_in[3];
    const float* wo = (const float*)d_in[4];
    float* out = (float*)d_out;

    __half *xh, *xl, *wqh, *wkh, *wvh, *woh;
    __half *Qh, *Ql, *Kh, *Vh, *Ch, *Cl;
    cudaGetSymbolAddress((void**)&xh, g_xh);
    cudaGetSymbolAddress((void**)&xl, g_xl);
    cudaGetSymbolAddress((void**)&wqh, g_wqh);
    cudaGetSymbolAddress((void**)&wkh, g_wkh);
    cudaGetSymbolAddress((void**)&wvh, g_wvh);
    cudaGetSymbolAddress((void**)&woh, g_woh);
    cudaGetSymbolAddress((void**)&Qh, g_Qh);
    cudaGetSymbolAddress((void**)&Ql, g_Ql);
    cudaGetSymbolAddress((void**)&Kh, g_Kh);
    cudaGetSymbolAddress((void**)&Vh, g_Vh);
    cudaGetSymbolAddress((void**)&Ch, g_Ch);
    cudaGetSymbolAddress((void**)&Cl, g_Cl);

    cudaFuncSetAttribute(gemm_qkv_kernel,
                         cudaFuncAttributeMaxDynamicSharedMemorySize, GEMM_SMEM);
    cudaFuncSetAttribute(gemm_o_kernel,
                         cudaFuncAttributeMaxDynamicSharedMemorySize, GEMM_SMEM);
    cudaFuncSetAttribute(flash_mma_kernel,
                         cudaFuncAttributeMaxDynamicSharedMemorySize, FLASH_SMEM);

    const int nx4 = M_TOTAL * D_MODEL / 4;
    const int nw4 = D_MODEL * D_MODEL / 4;

    split_kernel<<<(nx4 + 255) / 256, 256>>>((const float4*)x, (uint2*)xh, (uint2*)xl, nx4);
    roundw_kernel<<<dim3((nw4 + 255) / 256, 4), 256>>>(
        (const float4*)wq, (const float4*)wk, (const float4*)wv, (const float4*)wo,
        (uint2*)wqh, (uint2*)wkh, (uint2*)wvh, (uint2*)woh, nw4);

    gemm_qkv_kernel<<<dim3(D_MODEL / 128, M_TOTAL / 128, 3), 256, GEMM_SMEM>>>(
        xh, xl, wqh, wkh, wvh, Qh, Ql, Kh, Vh);

    flash_mma_kernel<<<dim3(SEQ / TQF, BATCH * NUM_HEADS), 256, FLASH_SMEM>>>(
        Qh, Ql, Kh, Vh, Ch, Cl);

    gemm_o_kernel<<<dim3(D_MODEL / 128, M_TOTAL / 128), 256, GEMM_SMEM>>>(
        Ch, Cl, woh, out);
}

// round 8
// speedup vs baseline: 6.7760x; 1.3583x over previous
#include <cuda_runtime.h>
#include <cuda_fp16.h>
#include <cstdint>
#include <math.h>

#define D_MODEL   2048
#define NUM_HEADS 16
#define HEAD_DIM  128
#define BATCH     2
#define SEQ       2048
#define M_TOTAL   (BATCH * SEQ)   // 4096

// ---------------- scratch (static device globals: no allocation allowed) ----
__device__ __half g_xh[M_TOTAL * D_MODEL];
__device__ __half g_xl[M_TOTAL * D_MODEL];
__device__ __half g_wqh[D_MODEL * D_MODEL];
__device__ __half g_wkh[D_MODEL * D_MODEL];
__device__ __half g_wvh[D_MODEL * D_MODEL];
__device__ __half g_woh[D_MODEL * D_MODEL];
__device__ __half g_Qh[M_TOTAL * D_MODEL];
__device__ __half g_Ql[M_TOTAL * D_MODEL];
__device__ __half g_Kh[M_TOTAL * D_MODEL];
__device__ __half g_Vh[M_TOTAL * D_MODEL];
__device__ __half g_Ch[M_TOTAL * D_MODEL];

// ============================================================================
// helpers
// ============================================================================
__device__ __forceinline__ uint32_t smem_u32(const void* p) {
    uint32_t a;
    asm("{ .reg .u64 t; cvta.to.shared.u64 t, %1; cvt.u32.u64 %0, t; }"
        : "=r"(a) : "l"(p));
    return a;
}
#define SW128(o) ((o) ^ (((o) >> 3) & 0x70))

__device__ __forceinline__ void ldsm4(uint32_t* r, uint32_t addr) {
    asm volatile("ldmatrix.sync.aligned.m8n8.x4.shared.b16 {%0,%1,%2,%3}, [%4];"
                 : "=r"(r[0]), "=r"(r[1]), "=r"(r[2]), "=r"(r[3]) : "r"(addr));
}
__device__ __forceinline__ void ldsm4t(uint32_t* r, uint32_t addr) {
    asm volatile("ldmatrix.sync.aligned.m8n8.x4.trans.shared.b16 {%0,%1,%2,%3}, [%4];"
                 : "=r"(r[0]), "=r"(r[1]), "=r"(r[2]), "=r"(r[3]) : "r"(addr));
}
__device__ __forceinline__ void mma16816(float* d, const uint32_t* a,
                                         const uint32_t* b) {
    asm volatile(
        "mma.sync.aligned.m16n8k16.row.col.f32.f16.f16.f32 "
        "{%0,%1,%2,%3}, {%4,%5,%6,%7}, {%8,%9}, {%0,%1,%2,%3};"
        : "+f"(d[0]), "+f"(d[1]), "+f"(d[2]), "+f"(d[3])
        : "r"(a[0]), "r"(a[1]), "r"(a[2]), "r"(a[3]), "r"(b[0]), "r"(b[1]));
}
__device__ __forceinline__ void cpasync16(uint32_t dst, const void* src) {
    asm volatile("cp.async.cg.shared.global [%0], [%1], 16;"
                 :: "r"(dst), "l"(src) : "memory");
}
#define CP_COMMIT() asm volatile("cp.async.commit_group;" ::: "memory")
#define CP_WAIT2()  asm volatile("cp.async.wait_group 2;" ::: "memory")
#define CP_WAIT1()  asm volatile("cp.async.wait_group 1;" ::: "memory")
#define CP_WAIT0()  asm volatile("cp.async.wait_group 0;" ::: "memory")

// fp32 pair -> fp16x2 hi + fp16x2 lo (residual)
__device__ __forceinline__ void split2h(float a, float b, uint32_t& hi, uint32_t& lo) {
    __half2 h = __floats2half2_rn(a, b);
    hi = *(uint32_t*)&h;
    float ra = a - __half2float(h.x);
    float rb = b - __half2float(h.y);
    __half2 l = __floats2half2_rn(ra, rb);
    lo = *(uint32_t*)&l;
}
__device__ __forceinline__ uint32_t pack2h(float a, float b) {
    __half2 h = __floats2half2_rn(a, b);
    return *(uint32_t*)&h;
}

// fast 2^y on the FMA/ALU pipes (no MUFU). y <= ~0; -inf -> 0.
__device__ __forceinline__ float fexp2(float y) {
    y = fmaxf(y, -120.f);
    const float t = y + 12582912.f;          // 1.5*2^23: round(y) in mantissa
    const int   i = __float_as_int(t);
    const float f = y - (t - 12582912.f);    // f in [-0.5, 0.5]
    float p = 1.33335581e-3f;
    p = fmaf(p, f, 9.61812910e-3f);
    p = fmaf(p, f, 5.55041087e-2f);
    p = fmaf(p, f, 2.40226507e-1f);
    p = fmaf(p, f, 6.93147181e-1f);
    p = fmaf(p, f, 1.0f);
    return __int_as_float(__float_as_int(p) + (i << 23));
}

// ============================================================================
// split kernels
// ============================================================================
__global__ __launch_bounds__(256)
void split_kernel(const float4* __restrict__ src, uint2* __restrict__ hi,
                  uint2* __restrict__ lo, int n4)
{
    int i = blockIdx.x * blockDim.x + threadIdx.x;
    if (i >= n4) return;
    float4 x = src[i];
    uint2 ho, lv;
    split2h(x.x, x.y, ho.x, lv.x);
    split2h(x.z, x.w, ho.y, lv.y);
    hi[i] = ho;
    lo[i] = lv;
}

__global__ __launch_bounds__(256)
void roundw_kernel(const float4* __restrict__ wq, const float4* __restrict__ wk,
                   const float4* __restrict__ wv, const float4* __restrict__ wo,
                   uint2* qh, uint2* kh, uint2* vh, uint2* oh, int n4)
{
    int i = blockIdx.x * blockDim.x + threadIdx.x;
    if (i >= n4) return;
    const float4* s; uint2* h;
    switch (blockIdx.y) {
        case 0:  s = wq; h = qh; break;
        case 1:  s = wk; h = kh; break;
        case 2:  s = wv; h = vh; break;
        default: s = wo; h = oh; break;
    }
    float4 x = s[i];
    uint2 ho;
    ho.x = pack2h(x.x, x.y);
    ho.y = pack2h(x.z, x.w);
    h[i] = ho;
}

// ============================================================================
// Tensor-core GEMM (NT) body, cp.async 3-stage.
//   NTERMS=2: C ~= Ah*Bh + Al*Bh ; NTERMS=1: C ~= Ah*Bh (fp32 accum)
// CTA 128x128, K chunk 64, 8 warps (warp 64x32).
// MODE: 0 = fp32 C, 1 = split hi/lo fp16, 2 = rounded fp16
// ============================================================================
#define TKF 64
#define NCHUNK (D_MODEL / TKF)     // 32

template<int NTERMS, int MODE>
__device__ __forceinline__
void gemm_body(const __half* __restrict__ Ah,
               const __half* __restrict__ Al,
               const __half* __restrict__ Bh,
               float* __restrict__ C,
               __half* __restrict__ Ch,
               __half* __restrict__ Cl,
               char* smc)
{
    constexpr int NT = NTERMS + 1;               // tiles per stage
    constexpr uint32_t STAGE = (uint32_t)NT * 16384u;
    constexpr uint32_t AL_OFF = 16384u;
    constexpr uint32_t B_OFF  = (uint32_t)(NT - 1) * 16384u;

    const uint32_t sb = smem_u32(smc);
    const int tid  = threadIdx.x;
    const int wid  = tid >> 5;
    const int lane = tid & 31;
    const int bN = blockIdx.x * 128;
    const int bM = blockIdx.y * 128;
    const int wm = (wid & 1) * 64;
    const int wn = (wid >> 1) * 32;

    const int a_row = wm + (lane & 15);
    const int a_kh  = (lane >> 4) * 8;
    const int b_jg  = (lane >> 4);
    const int b_kh  = ((lane >> 3) & 1) * 8;
    const int b_r8  = lane & 7;

    const __half* srcs[3];
    srcs[0] = Ah + (size_t)bM * D_MODEL;
    srcs[1] = (NTERMS == 2) ? (Al + (size_t)bM * D_MODEL)
                            : (Bh + (size_t)bN * D_MODEL);
    srcs[2] = Bh + (size_t)bN * D_MODEL;

    auto prefetch = [&](int c, int stage) {
        const int k0 = c * TKF;
        const uint32_t base = sb + stage * STAGE;
#pragma unroll
        for (int t = 0; t < NT; t++) {
            const __half* s = srcs[t] + k0;
#pragma unroll
            for (int it = 0; it < 4; it++) {
                const int vec = tid + it * 256;
                const int r = vec >> 3, v = vec & 7;
                cpasync16(base + t * 16384 + SW128((uint32_t)(r * 128 + v * 16)),
                          s + (size_t)r * D_MODEL + v * 8);
            }
        }
    };

    float acc[4][4][4] = {};

    prefetch(0, 0); CP_COMMIT();
    prefetch(1, 1); CP_COMMIT();

    for (int c = 0; c < NCHUNK; c++) {
        if (c + 2 < NCHUNK)      { prefetch(c + 2, (c + 2) % 3); CP_COMMIT(); CP_WAIT2(); }
        else if (c + 1 < NCHUNK) { CP_WAIT1(); }
        else                     { CP_WAIT0(); }
        __syncthreads();

        const uint32_t st = sb + (c % 3) * STAGE;
#pragma unroll
        for (int ks = 0; ks < 4; ks++) {
            const int k16 = ks * 16;
            uint32_t ahf[4][4], bf[4][2];
#pragma unroll
            for (int i = 0; i < 4; i++)
                ldsm4(ahf[i], st +
                      SW128((uint32_t)((a_row + i * 16) * 128 + (k16 + a_kh) * 2)));
#pragma unroll
            for (int p = 0; p < 2; p++) {
                uint32_t r[4];
                const int jr = wn + (p * 2 + b_jg) * 8 + b_r8;
                ldsm4(r, st + B_OFF + SW128((uint32_t)(jr * 128 + (k16 + b_kh) * 2)));
                bf[p * 2 + 0][0] = r[0]; bf[p * 2 + 0][1] = r[1];
                bf[p * 2 + 1][0] = r[2]; bf[p * 2 + 1][1] = r[3];
            }
#pragma unroll
            for (int i = 0; i < 4; i++)
#pragma unroll
                for (int j = 0; j < 4; j++)
                    mma16816(acc[i][j], ahf[i], bf[j]);
            if (NTERMS == 2) {
                uint32_t alf[4][4];
#pragma unroll
                for (int i = 0; i < 4; i++)
                    ldsm4(alf[i], st + AL_OFF +
                          SW128((uint32_t)((a_row + i * 16) * 128 + (k16 + a_kh) * 2)));
#pragma unroll
                for (int i = 0; i < 4; i++)
#pragma unroll
                    for (int j = 0; j < 4; j++)
                        mma16816(acc[i][j], alf[i], bf[j]);
            }
        }
        __syncthreads();
    }

    const int er = bM + wm + (lane >> 2);
    const int ec = bN + wn + (lane & 3) * 2;
#pragma unroll
    for (int i = 0; i < 4; i++)
#pragma unroll
        for (int j = 0; j < 4; j++) {
            const size_t o0 = (size_t)(er + i * 16) * D_MODEL + ec + j * 8;
            const size_t o1 = (size_t)(er + i * 16 + 8) * D_MODEL + ec + j * 8;
            if (MODE == 0) {
                *(float2*)&C[o0] = make_float2(acc[i][j][0], acc[i][j][1]);
                *(float2*)&C[o1] = make_float2(acc[i][j][2], acc[i][j][3]);
            } else if (MODE == 1) {
                uint32_t h, l;
                split2h(acc[i][j][0], acc[i][j][1], h, l);
                *(uint32_t*)&Ch[o0] = h; *(uint32_t*)&Cl[o0] = l;
                split2h(acc[i][j][2], acc[i][j][3], h, l);
                *(uint32_t*)&Ch[o1] = h; *(uint32_t*)&Cl[o1] = l;
            } else {
                *(uint32_t*)&Ch[o0] = pack2h(acc[i][j][0], acc[i][j][1]);
                *(uint32_t*)&Ch[o1] = pack2h(acc[i][j][2], acc[i][j][3]);
            }
        }
}

#define GEMM_SMEM_2T (3 * 49152)   // 147456
#define GEMM_SMEM_1T (3 * 32768)   // 98304

// Q projection: 2-term input, split hi/lo output
__global__ __launch_bounds__(256, 1)
void gemm_q_kernel(const __half* __restrict__ xh, const __half* __restrict__ xl,
                   const __half* __restrict__ wqh,
                   __half* __restrict__ Qh, __half* __restrict__ Ql)
{
    extern __shared__ char smc[];
    gemm_body<2, 1>(xh, xl, wqh, nullptr, Qh, Ql, smc);
}

// K/V projections: 1-term input, rounded output; z selects K or V
__global__ __launch_bounds__(256, 1)
void gemm_kv_kernel(const __half* __restrict__ xh,
                    const __half* __restrict__ wkh, const __half* __restrict__ wvh,
                    __half* __restrict__ Kh, __half* __restrict__ Vh)
{
    extern __shared__ char smc[];
    if (blockIdx.z == 0)
        gemm_body<1, 2>(xh, nullptr, wkh, nullptr, Kh, nullptr, smc);
    else
        gemm_body<1, 2>(xh, nullptr, wvh, nullptr, Vh, nullptr, smc);
}

// O projection: 1-term input, fp32 output
__global__ __launch_bounds__(256, 1)
void gemm_o_kernel(const __half* __restrict__ Ch, const __half* __restrict__ woh,
                   float* __restrict__ C)
{
    extern __shared__ char smc[];
    gemm_body<1, 0>(Ch, nullptr, woh, C, nullptr, nullptr, smc);
}

// ============================================================================
// Causal flash attention, mma.sync fp16 2-term (Q and P split; K,V rounded),
// base-2 softmax on FMA pipe, cp.async double-buffered K/V.
// CTA = 128 q-rows x full head, K tile 64. Smem 128KB. 8 warps.
// ============================================================================
#define TQF 128
#define TKN 64
#define FQ_BASE  0
#define FKV_BASE 65536
#define KV_STAGE 32768
#define FLASH_SMEM (FKV_BASE + 2 * KV_STAGE)   // 131072

__global__ __launch_bounds__(256, 1)
void flash_mma_kernel(const __half* __restrict__ Qh, const __half* __restrict__ Ql,
                      const __half* __restrict__ Kh, const __half* __restrict__ Vh,
                      __half* __restrict__ Ch)
{
    extern __shared__ char smf[];
    const uint32_t sb = smem_u32(smf);
    const int tid  = threadIdx.x;
    const int wid  = tid >> 5;
    const int lane = tid & 31;

    // grid (bh, qt'): globally heavy-first causal schedule
    const int bh = blockIdx.x;
    const int qt = (int)(gridDim.y - 1) - (int)blockIdx.y;
    const int b  = bh >> 4;
    const int h  = bh & 15;
    const int q0 = qt * TQF;
    const float C2 = 0.08838834764831845f * 1.4426950408889634f; // scale*log2e

    const size_t qbase  = ((size_t)(b * SEQ + q0)) * D_MODEL + h * HEAD_DIM;
    const size_t kvbase = ((size_t)(b * SEQ)) * D_MODEL + h * HEAD_DIM;

    const int nkt = 2 * qt + 2;

    auto prefetch_kv = [&](int kt, int stage) {
        const int k0 = kt * TKN;
        const uint32_t st = sb + FKV_BASE + stage * KV_STAGE;
        for (int i = tid; i < TKN * 16; i += 256) {
            const int r = i >> 4, v = i & 15;
            const size_t g = kvbase + (size_t)(k0 + r) * D_MODEL + v * 8;
            const uint32_t so = (uint32_t)((v >> 3) * 8192)
                              + SW128((uint32_t)(r * 128 + (v & 7) * 16));
            cpasync16(st + so,         Kh + g);
            cpasync16(st + 16384 + so, Vh + g);
        }
    };

    // ---- load Q tile (hi+lo), subtiles split at d=64 ----
    for (int i = tid; i < TQF * 16; i += 256) {
        const int r = i >> 4, v = i & 15;
        const uint32_t so = (uint32_t)((v >> 3) * 16384)
                          + SW128((uint32_t)(r * 128 + (v & 7) * 16));
        *(uint4*)(smf + FQ_BASE + so) =
            *(const uint4*)(Qh + qbase + (size_t)r * D_MODEL + v * 8);
        *(uint4*)(smf + FQ_BASE + 32768 + so) =
            *(const uint4*)(Ql + qbase + (size_t)r * D_MODEL + v * 8);
    }
    prefetch_kv(0, 0);
    CP_COMMIT();

    const int wm = wid * 16;
    const int a_row = wm + (lane & 15);
    const int a_kh  = (lane >> 4) * 8;

    float oacc[16][4] = {};
    float m0 = -INFINITY, m1 = -INFINITY, l0 = 0.f, l1 = 0.f;

    for (int kt = 0; kt < nkt; kt++) {
        const int k0 = kt * TKN;
        if (kt + 1 < nkt) { prefetch_kv(kt + 1, (kt + 1) & 1); CP_COMMIT(); CP_WAIT1(); }
        else              { CP_WAIT0(); }
        __syncthreads();
        const uint32_t st = sb + FKV_BASE + (kt & 1) * KV_STAGE;

        // ---- S = Q K^T (2-term: Qh*Kh + Ql*Kh) ----
        float sacc[8][4] = {};
#pragma unroll
        for (int s = 0; s < 8; s++) {
            const int sub = s >> 2, kb = (s & 3) * 16;
            const uint32_t qoff = (uint32_t)(sub * 16384) +
                SW128((uint32_t)(a_row * 128 + (kb + a_kh) * 2));
            uint32_t qhf[4], qlf[4], kf[8][2];
            ldsm4(qhf, sb + FQ_BASE + qoff);
            ldsm4(qlf, sb + FQ_BASE + 32768 + qoff);
#pragma unroll
            for (int p = 0; p < 4; p++) {
                uint32_t r[4];
                const int jr = (p * 2 + (lane >> 4)) * 8 + (lane & 7);
                ldsm4(r, st + sub * 8192 +
                      SW128((uint32_t)(jr * 128 + (kb + ((lane >> 3) & 1) * 8) * 2)));
                kf[p * 2 + 0][0] = r[0]; kf[p * 2 + 0][1] = r[1];
                kf[p * 2 + 1][0] = r[2]; kf[p * 2 + 1][1] = r[3];
            }
#pragma unroll
            for (int j = 0; j < 8; j++) mma16816(sacc[j], qhf, kf[j]);
#pragma unroll
            for (int j = 0; j < 8; j++) mma16816(sacc[j], qlf, kf[j]);
        }

        // ---- scale (base-2) + causal mask ----
        const bool needmask = (k0 + TKN - 1) > (q0 + wm);
        const int rl = lane >> 2, cl = (lane & 3) * 2;
#pragma unroll
        for (int j = 0; j < 8; j++)
#pragma unroll
            for (int e = 0; e < 4; e++) {
                float v = sacc[j][e] * C2;
                if (needmask) {
                    const int colg = k0 + 8 * j + cl + (e & 1);
                    const int rowg = q0 + wm + rl + (e >> 1) * 8;
                    if (colg > rowg) v = -INFINITY;
                }
                sacc[j][e] = v;
            }

        // ---- online softmax (exp2 on FMA pipe) ----
        float mt0 = -INFINITY, mt1 = -INFINITY;
#pragma unroll
        for (int j = 0; j < 8; j++) {
            mt0 = fmaxf(mt0, fmaxf(sacc[j][0], sacc[j][1]));
            mt1 = fmaxf(mt1, fmaxf(sacc[j][2], sacc[j][3]));
        }
        mt0 = fmaxf(mt0, __shfl_xor_sync(0xFFFFFFFFu, mt0, 1));
        mt0 = fmaxf(mt0, __shfl_xor_sync(0xFFFFFFFFu, mt0, 2));
        mt1 = fmaxf(mt1, __shfl_xor_sync(0xFFFFFFFFu, mt1, 1));
        mt1 = fmaxf(mt1, __shfl_xor_sync(0xFFFFFFFFu, mt1, 2));
        const float mn0 = fmaxf(m0, mt0), mn1 = fmaxf(m1, mt1);
        const float al0 = fexp2(m0 - mn0), al1 = fexp2(m1 - mn1);
        float s0 = 0.f, s1 = 0.f;
#pragma unroll
        for (int j = 0; j < 8; j++) {
            sacc[j][0] = fexp2(sacc[j][0] - mn0); s0 += sacc[j][0];
            sacc[j][1] = fexp2(sacc[j][1] - mn0); s0 += sacc[j][1];
            sacc[j][2] = fexp2(sacc[j][2] - mn1); s1 += sacc[j][2];
            sacc[j][3] = fexp2(sacc[j][3] - mn1); s1 += sacc[j][3];
        }
        s0 += __shfl_xor_sync(0xFFFFFFFFu, s0, 1);
        s0 += __shfl_xor_sync(0xFFFFFFFFu, s0, 2);
        s1 += __shfl_xor_sync(0xFFFFFFFFu, s1, 1);
        s1 += __shfl_xor_sync(0xFFFFFFFFu, s1, 2);
        l0 = l0 * al0 + s0;
        l1 = l1 * al1 + s1;
        m0 = mn0; m1 = mn1;
#pragma unroll
        for (int j = 0; j < 16; j++) {
            oacc[j][0] *= al0; oacc[j][1] *= al0;
            oacc[j][2] *= al1; oacc[j][3] *= al1;
        }

        // ---- O += P V (2-term: Ph*Vh + Pl*Vh), V^T via ldmatrix.trans ----
#pragma unroll
        for (int s2 = 0; s2 < 4; s2++) {
            uint32_t ph[4], pl[4];
            split2h(sacc[2 * s2][0],     sacc[2 * s2][1],     ph[0], pl[0]);
            split2h(sacc[2 * s2][2],     sacc[2 * s2][3],     ph[1], pl[1]);
            split2h(sacc[2 * s2 + 1][0], sacc[2 * s2 + 1][1], ph[2], pl[2]);
            split2h(sacc[2 * s2 + 1][2], sacc[2 * s2 + 1][3], ph[3], pl[3]);
            const int vrow = 16 * s2 + ((lane >> 3) & 1) * 8 + (lane & 7);
#pragma unroll
            for (int p = 0; p < 8; p++) {
                const uint32_t voff = (uint32_t)((p >> 2) * 8192) +
                    SW128((uint32_t)(vrow * 128 + 32 * (p & 3) + (lane >> 4) * 16));
                uint32_t r[4];
                ldsm4t(r, st + 16384 + voff);
                uint32_t b0[2] = { r[0], r[1] }, b1[2] = { r[2], r[3] };
                mma16816(oacc[2 * p],     ph, b0);
                mma16816(oacc[2 * p + 1], ph, b1);
                mma16816(oacc[2 * p],     pl, b0);
                mma16816(oacc[2 * p + 1], pl, b1);
            }
        }
        __syncthreads();   // all warps done reading this stage before overwrite
    }

    // ---- epilogue: normalize, round to fp16, store CTX ----
    const float li0 = 1.f / l0, li1 = 1.f / l1;
    const int r0 = q0 + wm + (lane >> 2);
    const int cbase = h * HEAD_DIM + (lane & 3) * 2;
#pragma unroll
    for (int j = 0; j < 16; j++) {
        const size_t o0 = ((size_t)(b * SEQ + r0)) * D_MODEL + cbase + 8 * j;
        const size_t o1 = ((size_t)(b * SEQ + r0 + 8)) * D_MODEL + cbase + 8 * j;
        *(uint32_t*)&Ch[o0] = pack2h(oacc[j][0] * li0, oacc[j][1] * li0);
        *(uint32_t*)&Ch[o1] = pack2h(oacc[j][2] * li1, oacc[j][3] * li1);
    }
}

// ============================================================================
// launch
// ============================================================================
extern "C" void kernel_launch(void* const* d_in, const int* in_sizes, int n_in,
                              void* d_out, int out_size)
{
    const float* x  = (const float*)d_in[0];
    const float* wq = (const float*)d_in[1];
    const float* wk = (const float*)d_in[2];
    const float* wv = (const float*)d_in[3];
    const float* wo = (const float*)d_in[4];
    float* out = (float*)d_out;

    __half *xh, *xl, *wqh, *wkh, *wvh, *woh;
    __half *Qh, *Ql, *Kh, *Vh, *Ch;
    cudaGetSymbolAddress((void**)&xh, g_xh);
    cudaGetSymbolAddress((void**)&xl, g_xl);
    cudaGetSymbolAddress((void**)&wqh, g_wqh);
    cudaGetSymbolAddress((void**)&wkh, g_wkh);
    cudaGetSymbolAddress((void**)&wvh, g_wvh);
    cudaGetSymbolAddress((void**)&woh, g_woh);
    cudaGetSymbolAddress((void**)&Qh, g_Qh);
    cudaGetSymbolAddress((void**)&Ql, g_Ql);
    cudaGetSymbolAddress((void**)&Kh, g_Kh);
    cudaGetSymbolAddress((void**)&Vh, g_Vh);
    cudaGetSymbolAddress((void**)&Ch, g_Ch);

    cudaFuncSetAttribute(gemm_q_kernel,
                         cudaFuncAttributeMaxDynamicSharedMemorySize, GEMM_SMEM_2T);
    cudaFuncSetAttribute(gemm_kv_kernel,
                         cudaFuncAttributeMaxDynamicSharedMemorySize, GEMM_SMEM_1T);
    cudaFuncSetAttribute(gemm_o_kernel,
                         cudaFuncAttributeMaxDynamicSharedMemorySize, GEMM_SMEM_1T);
    cudaFuncSetAttribute(flash_mma_kernel,
                         cudaFuncAttributeMaxDynamicSharedMemorySize, FLASH_SMEM);

    const int nx4 = M_TOTAL * D_MODEL / 4;
    const int nw4 = D_MODEL * D_MODEL / 4;
    dim3 gg(D_MODEL / 128, M_TOTAL / 128);   // (16, 32)

    split_kernel<<<(nx4 + 255) / 256, 256>>>((const float4*)x, (uint2*)xh, (uint2*)xl, nx4);
    roundw_kernel<<<dim3((nw4 + 255) / 256, 4), 256>>>(
        (const float4*)wq, (const float4*)wk, (const float4*)wv, (const float4*)wo,
        (uint2*)wqh, (uint2*)wkh, (uint2*)wvh, (uint2*)woh, nw4);

    gemm_q_kernel<<<gg, 256, GEMM_SMEM_2T>>>(xh, xl, wqh, Qh, Ql);
    gemm_kv_kernel<<<dim3(gg.x, gg.y, 2), 256, GEMM_SMEM_1T>>>(xh, wkh, wvh, Kh, Vh);

    flash_mma_kernel<<<dim3(BATCH * NUM_HEADS, SEQ / TQF), 256, FLASH_SMEM>>>(
        Qh, Ql, Kh, Vh, Ch);

    gemm_o_kernel<<<gg, 256, GEMM_SMEM_1T>>>(Ch, woh, out);
}

// round 12
// speedup vs baseline: 7.4602x; 1.1010x over previous
#include <cuda_runtime.h>
#include <cuda_fp16.h>
#include <cstdint>
#include <math.h>

#define D_MODEL   2048
#define NUM_HEADS 16
#define HEAD_DIM  128
#define BATCH     2
#define SEQ       2048
#define M_TOTAL   (BATCH * SEQ)   // 4096

// ---------------- scratch (static device globals: no allocation allowed) ----
__device__ __half g_xh[M_TOTAL * D_MODEL];
__device__ __half g_xl[M_TOTAL * D_MODEL];
__device__ __half g_wqh[D_MODEL * D_MODEL];
__device__ __half g_wkh[D_MODEL * D_MODEL];
__device__ __half g_wvh[D_MODEL * D_MODEL];
__device__ __half g_woh[D_MODEL * D_MODEL];
__device__ __half g_Qh[M_TOTAL * D_MODEL];
__device__ __half g_Ql[M_TOTAL * D_MODEL];
__device__ __half g_Kh[M_TOTAL * D_MODEL];
__device__ __half g_Vh[M_TOTAL * D_MODEL];
__device__ __half g_Ch[M_TOTAL * D_MODEL];

// ============================================================================
// helpers
// ============================================================================
__device__ __forceinline__ uint32_t smem_u32(const void* p) {
    uint32_t a;
    asm("{ .reg .u64 t; cvta.to.shared.u64 t, %1; cvt.u32.u64 %0, t; }"
        : "=r"(a) : "l"(p));
    return a;
}
#define SW128(o) ((o) ^ (((o) >> 3) & 0x70))

__device__ __forceinline__ void ldsm4(uint32_t* r, uint32_t addr) {
    asm volatile("ldmatrix.sync.aligned.m8n8.x4.shared.b16 {%0,%1,%2,%3}, [%4];"
                 : "=r"(r[0]), "=r"(r[1]), "=r"(r[2]), "=r"(r[3]) : "r"(addr));
}
__device__ __forceinline__ void ldsm4t(uint32_t* r, uint32_t addr) {
    asm volatile("ldmatrix.sync.aligned.m8n8.x4.trans.shared.b16 {%0,%1,%2,%3}, [%4];"
                 : "=r"(r[0]), "=r"(r[1]), "=r"(r[2]), "=r"(r[3]) : "r"(addr));
}
__device__ __forceinline__ void mma16816(float* d, const uint32_t* a,
                                         const uint32_t* b) {
    asm volatile(
        "mma.sync.aligned.m16n8k16.row.col.f32.f16.f16.f32 "
        "{%0,%1,%2,%3}, {%4,%5,%6,%7}, {%8,%9}, {%0,%1,%2,%3};"
        : "+f"(d[0]), "+f"(d[1]), "+f"(d[2]), "+f"(d[3])
        : "r"(a[0]), "r"(a[1]), "r"(a[2]), "r"(a[3]), "r"(b[0]), "r"(b[1]));
}
__device__ __forceinline__ void cpasync16(uint32_t dst, const void* src) {
    asm volatile("cp.async.cg.shared.global [%0], [%1], 16;"
                 :: "r"(dst), "l"(src) : "memory");
}
#define CP_COMMIT() asm volatile("cp.async.commit_group;" ::: "memory")
#define CP_WAIT2()  asm volatile("cp.async.wait_group 2;" ::: "memory")
#define CP_WAIT1()  asm volatile("cp.async.wait_group 1;" ::: "memory")
#define CP_WAIT0()  asm volatile("cp.async.wait_group 0;" ::: "memory")

// fp32 pair -> fp16x2 hi + fp16x2 lo (residual)
__device__ __forceinline__ void split2h(float a, float b, uint32_t& hi, uint32_t& lo) {
    __half2 h = __floats2half2_rn(a, b);
    hi = *(uint32_t*)&h;
    float ra = a - __half2float(h.x);
    float rb = b - __half2float(h.y);
    __half2 l = __floats2half2_rn(ra, rb);
    lo = *(uint32_t*)&l;
}
__device__ __forceinline__ uint32_t pack2h(float a, float b) {
    __half2 h = __floats2half2_rn(a, b);
    return *(uint32_t*)&h;
}

// fast 2^y on the FMA/ALU pipes (no MUFU). y <= ~0; -inf -> 0.
__device__ __forceinline__ float fexp2(float y) {
    y = fmaxf(y, -120.f);
    const float t = y + 12582912.f;          // 1.5*2^23: round(y) in mantissa
    const int   i = __float_as_int(t);
    const float f = y - (t - 12582912.f);    // f in [-0.5, 0.5]
    float p = 1.33335581e-3f;
    p = fmaf(p, f, 9.61812910e-3f);
    p = fmaf(p, f, 5.55041087e-2f);
    p = fmaf(p, f, 2.40226507e-1f);
    p = fmaf(p, f, 6.93147181e-1f);
    p = fmaf(p, f, 1.0f);
    return __int_as_float(__float_as_int(p) + (i << 23));
}

// ============================================================================
// split kernels
// ============================================================================
__global__ __launch_bounds__(256)
void split_kernel(const float4* __restrict__ src, uint2* __restrict__ hi,
                  uint2* __restrict__ lo, int n4)
{
    int i = blockIdx.x * blockDim.x + threadIdx.x;
    if (i >= n4) return;
    float4 x = src[i];
    uint2 ho, lv;
    split2h(x.x, x.y, ho.x, lv.x);
    split2h(x.z, x.w, ho.y, lv.y);
    hi[i] = ho;
    lo[i] = lv;
}

__global__ __launch_bounds__(256)
void roundw_kernel(const float4* __restrict__ wq, const float4* __restrict__ wk,
                   const float4* __restrict__ wv, const float4* __restrict__ wo,
                   uint2* qh, uint2* kh, uint2* vh, uint2* oh, int n4)
{
    int i = blockIdx.x * blockDim.x + threadIdx.x;
    if (i >= n4) return;
    const float4* s; uint2* h;
    switch (blockIdx.y) {
        case 0:  s = wq; h = qh; break;
        case 1:  s = wk; h = kh; break;
        case 2:  s = wv; h = vh; break;
        default: s = wo; h = oh; break;
    }
    float4 x = s[i];
    uint2 ho;
    ho.x = pack2h(x.x, x.y);
    ho.y = pack2h(x.z, x.w);
    h[i] = ho;
}

// ============================================================================
// Tensor-core GEMM (NT) body, cp.async multi-stage.
//   NTERMS=2: C ~= Ah*Bh + Al*Bh ; NTERMS=1: C ~= Ah*Bh (fp32 accum)
// CTA 128x128, K chunk 64. 4 warps (128 thr), warp tile 64x64 -> 2 CTAs/SM.
// MODE: 0 = fp32 C, 1 = split hi/lo fp16, 2 = rounded fp16
// ============================================================================
#define TKF 64
#define NCHUNK (D_MODEL / TKF)     // 32

template<int NTERMS, int MODE, int NSTAGES>
__device__ __forceinline__
void gemm_body(const __half* __restrict__ Ah,
               const __half* __restrict__ Al,
               const __half* __restrict__ Bh,
               float* __restrict__ C,
               __half* __restrict__ Ch,
               __half* __restrict__ Cl,
               char* smc)
{
    constexpr int NT = NTERMS + 1;               // tiles per stage
    constexpr uint32_t STAGE = (uint32_t)NT * 16384u;
    constexpr uint32_t AL_OFF = 16384u;
    constexpr uint32_t B_OFF  = (uint32_t)(NT - 1) * 16384u;

    const uint32_t sb = smem_u32(smc);
    const int tid  = threadIdx.x;
    const int wid  = tid >> 5;
    const int lane = tid & 31;
    const int bN = blockIdx.x * 128;
    const int bM = blockIdx.y * 128;
    const int wm = (wid & 1) * 64;
    const int wn = (wid >> 1) * 64;

    const int a_row = wm + (lane & 15);
    const int a_kh  = (lane >> 4) * 8;
    const int b_jg  = (lane >> 4);
    const int b_kh  = ((lane >> 3) & 1) * 8;
    const int b_r8  = lane & 7;

    const __half* srcs[3];
    srcs[0] = Ah + (size_t)bM * D_MODEL;
    srcs[1] = (NTERMS == 2) ? (Al + (size_t)bM * D_MODEL)
                            : (Bh + (size_t)bN * D_MODEL);
    srcs[2] = Bh + (size_t)bN * D_MODEL;

    auto prefetch = [&](int c, int stage) {
        const int k0 = c * TKF;
        const uint32_t base = sb + stage * STAGE;
#pragma unroll
        for (int t = 0; t < NT; t++) {
            const __half* s = srcs[t] + k0;
#pragma unroll
            for (int it = 0; it < 8; it++) {
                const int vec = tid + it * 128;
                const int r = vec >> 3, v = vec & 7;
                cpasync16(base + t * 16384 + SW128((uint32_t)(r * 128 + v * 16)),
                          s + (size_t)r * D_MODEL + v * 8);
            }
        }
    };

    float acc[4][8][4] = {};   // warp 64x64: [m-frag][n-frag][4]

    prefetch(0, 0); CP_COMMIT();
    if (NSTAGES == 3) { prefetch(1, 1); CP_COMMIT(); }

    for (int c = 0; c < NCHUNK; c++) {
        if (NSTAGES == 3) {
            if (c + 2 < NCHUNK)      { prefetch(c + 2, (c + 2) % 3); CP_COMMIT(); CP_WAIT2(); }
            else if (c + 1 < NCHUNK) { CP_WAIT1(); }
            else                     { CP_WAIT0(); }
        } else {
            if (c + 1 < NCHUNK) { prefetch(c + 1, (c + 1) & 1); CP_COMMIT(); CP_WAIT1(); }
            else                { CP_WAIT0(); }
        }
        __syncthreads();

        const uint32_t st = sb + (c % NSTAGES) * STAGE;
#pragma unroll
        for (int ks = 0; ks < 4; ks++) {
            const int k16 = ks * 16;
            uint32_t ahf[4][4], bf[8][2];
#pragma unroll
            for (int i = 0; i < 4; i++)
                ldsm4(ahf[i], st +
                      SW128((uint32_t)((a_row + i * 16) * 128 + (k16 + a_kh) * 2)));
#pragma unroll
            for (int p = 0; p < 4; p++) {
                uint32_t r[4];
                const int jr = wn + (p * 2 + b_jg) * 8 + b_r8;
                ldsm4(r, st + B_OFF + SW128((uint32_t)(jr * 128 + (k16 + b_kh) * 2)));
                bf[p * 2 + 0][0] = r[0]; bf[p * 2 + 0][1] = r[1];
                bf[p * 2 + 1][0] = r[2]; bf[p * 2 + 1][1] = r[3];
            }
#pragma unroll
            for (int i = 0; i < 4; i++)
#pragma unroll
                for (int j = 0; j < 8; j++)
                    mma16816(acc[i][j], ahf[i], bf[j]);
            if (NTERMS == 2) {
                uint32_t alf[4][4];
#pragma unroll
                for (int i = 0; i < 4; i++)
                    ldsm4(alf[i], st + AL_OFF +
                          SW128((uint32_t)((a_row + i * 16) * 128 + (k16 + a_kh) * 2)));
#pragma unroll
                for (int i = 0; i < 4; i++)
#pragma unroll
                    for (int j = 0; j < 8; j++)
                        mma16816(acc[i][j], alf[i], bf[j]);
            }
        }
        __syncthreads();
    }

    const int er = bM + wm + (lane >> 2);
    const int ec = bN + wn + (lane & 3) * 2;
#pragma unroll
    for (int i = 0; i < 4; i++)
#pragma unroll
        for (int j = 0; j < 8; j++) {
            const size_t o0 = (size_t)(er + i * 16) * D_MODEL + ec + j * 8;
            const size_t o1 = (size_t)(er + i * 16 + 8) * D_MODEL + ec + j * 8;
            if (MODE == 0) {
                *(float2*)&C[o0] = make_float2(acc[i][j][0], acc[i][j][1]);
                *(float2*)&C[o1] = make_float2(acc[i][j][2], acc[i][j][3]);
            } else if (MODE == 1) {
                uint32_t h, l;
                split2h(acc[i][j][0], acc[i][j][1], h, l);
                *(uint32_t*)&Ch[o0] = h; *(uint32_t*)&Cl[o0] = l;
                split2h(acc[i][j][2], acc[i][j][3], h, l);
                *(uint32_t*)&Ch[o1] = h; *(uint32_t*)&Cl[o1] = l;
            } else {
                *(uint32_t*)&Ch[o0] = pack2h(acc[i][j][0], acc[i][j][1]);
                *(uint32_t*)&Ch[o1] = pack2h(acc[i][j][2], acc[i][j][3]);
            }
        }
}

#define GEMM_SMEM_2T (2 * 49152)   // 98304 (2-stage, 2 CTAs/SM)
#define GEMM_SMEM_1T (3 * 32768)   // 98304 (3-stage, 2 CTAs/SM)

// Q projection: 2-term input, split hi/lo output
__global__ __launch_bounds__(128, 2)
void gemm_q_kernel(const __half* __restrict__ xh, const __half* __restrict__ xl,
                   const __half* __restrict__ wqh,
                   __half* __restrict__ Qh, __half* __restrict__ Ql)
{
    extern __shared__ char smc[];
    gemm_body<2, 1, 2>(xh, xl, wqh, nullptr, Qh, Ql, smc);
}

// K/V projections: 1-term input, rounded output; z selects K or V
__global__ __launch_bounds__(128, 2)
void gemm_kv_kernel(const __half* __restrict__ xh,
                    const __half* __restrict__ wkh, const __half* __restrict__ wvh,
                    __half* __restrict__ Kh, __half* __restrict__ Vh)
{
    extern __shared__ char smc[];
    if (blockIdx.z == 0)
        gemm_body<1, 2, 3>(xh, nullptr, wkh, nullptr, Kh, nullptr, smc);
    else
        gemm_body<1, 2, 3>(xh, nullptr, wvh, nullptr, Vh, nullptr, smc);
}

// O projection: 1-term input, fp32 output
__global__ __launch_bounds__(128, 2)
void gemm_o_kernel(const __half* __restrict__ Ch, const __half* __restrict__ woh,
                   float* __restrict__ C)
{
    extern __shared__ char smc[];
    gemm_body<1, 0, 3>(Ch, nullptr, woh, C, nullptr, nullptr, smc);
}

// ============================================================================
// Causal flash attention, mma.sync fp16 2-term (Q and P split; K,V rounded),
// base-2 softmax on FMA pipe, cp.async double-buffered K/V.
// CTA = 128 q-rows x full head, K tile 64. Smem 128KB. 8 warps. (unchanged)
// ============================================================================
#define TQF 128
#define TKN 64
#define FQ_BASE  0
#define FKV_BASE 65536
#define KV_STAGE 32768
#define FLASH_SMEM (FKV_BASE + 2 * KV_STAGE)   // 131072

__global__ __launch_bounds__(256, 1)
void flash_mma_kernel(const __half* __restrict__ Qh, const __half* __restrict__ Ql,
                      const __half* __restrict__ Kh, const __half* __restrict__ Vh,
                      __half* __restrict__ Ch)
{
    extern __shared__ char smf[];
    const uint32_t sb = smem_u32(smf);
    const int tid  = threadIdx.x;
    const int wid  = tid >> 5;
    const int lane = tid & 31;

    const int bh = blockIdx.x;
    const int qt = (int)(gridDim.y - 1) - (int)blockIdx.y;
    const int b  = bh >> 4;
    const int h  = bh & 15;
    const int q0 = qt * TQF;
    const float C2 = 0.08838834764831845f * 1.4426950408889634f; // scale*log2e

    const size_t qbase  = ((size_t)(b * SEQ + q0)) * D_MODEL + h * HEAD_DIM;
    const size_t kvbase = ((size_t)(b * SEQ)) * D_MODEL + h * HEAD_DIM;

    const int nkt = 2 * qt + 2;

    auto prefetch_kv = [&](int kt, int stage) {
        const int k0 = kt * TKN;
        const uint32_t st = sb + FKV_BASE + stage * KV_STAGE;
        for (int i = tid; i < TKN * 16; i += 256) {
            const int r = i >> 4, v = i & 15;
            const size_t g = kvbase + (size_t)(k0 + r) * D_MODEL + v * 8;
            const uint32_t so = (uint32_t)((v >> 3) * 8192)
                              + SW128((uint32_t)(r * 128 + (v & 7) * 16));
            cpasync16(st + so,         Kh + g);
            cpasync16(st + 16384 + so, Vh + g);
        }
    };

    for (int i = tid; i < TQF * 16; i += 256) {
        const int r = i >> 4, v = i & 15;
        const uint32_t so = (uint32_t)((v >> 3) * 16384)
                          + SW128((uint32_t)(r * 128 + (v & 7) * 16));
        *(uint4*)(smf + FQ_BASE + so) =
            *(const uint4*)(Qh + qbase + (size_t)r * D_MODEL + v * 8);
        *(uint4*)(smf + FQ_BASE + 32768 + so) =
            *(const uint4*)(Ql + qbase + (size_t)r * D_MODEL + v * 8);
    }
    prefetch_kv(0, 0);
    CP_COMMIT();

    const int wm = wid * 16;
    const int a_row = wm + (lane & 15);
    const int a_kh  = (lane >> 4) * 8;

    float oacc[16][4] = {};
    float m0 = -INFINITY, m1 = -INFINITY, l0 = 0.f, l1 = 0.f;

    for (int kt = 0; kt < nkt; kt++) {
        const int k0 = kt * TKN;
        if (kt + 1 < nkt) { prefetch_kv(kt + 1, (kt + 1) & 1); CP_COMMIT(); CP_WAIT1(); }
        else              { CP_WAIT0(); }
        __syncthreads();
        const uint32_t st = sb + FKV_BASE + (kt & 1) * KV_STAGE;

        float sacc[8][4] = {};
#pragma unroll
        for (int s = 0; s < 8; s++) {
            const int sub = s >> 2, kb = (s & 3) * 16;
            const uint32_t qoff = (uint32_t)(sub * 16384) +
                SW128((uint32_t)(a_row * 128 + (kb + a_kh) * 2));
            uint32_t qhf[4], qlf[4], kf[8][2];
            ldsm4(qhf, sb + FQ_BASE + qoff);
            ldsm4(qlf, sb + FQ_BASE + 32768 + qoff);
#pragma unroll
            for (int p = 0; p < 4; p++) {
                uint32_t r[4];
                const int jr = (p * 2 + (lane >> 4)) * 8 + (lane & 7);
                ldsm4(r, st + sub * 8192 +
                      SW128((uint32_t)(jr * 128 + (kb + ((lane >> 3) & 1) * 8) * 2)));
                kf[p * 2 + 0][0] = r[0]; kf[p * 2 + 0][1] = r[1];
                kf[p * 2 + 1][0] = r[2]; kf[p * 2 + 1][1] = r[3];
            }
#pragma unroll
            for (int j = 0; j < 8; j++) mma16816(sacc[j], qhf, kf[j]);
#pragma unroll
            for (int j = 0; j < 8; j++) mma16816(sacc[j], qlf, kf[j]);
        }

        const bool needmask = (k0 + TKN - 1) > (q0 + wm);
        const int rl = lane >> 2, cl = (lane & 3) * 2;
#pragma unroll
        for (int j = 0; j < 8; j++)
#pragma unroll
            for (int e = 0; e < 4; e++) {
                float v = sacc[j][e] * C2;
                if (needmask) {
                    const int colg = k0 + 8 * j + cl + (e & 1);
                    const int rowg = q0 + wm + rl + (e >> 1) * 8;
                    if (colg > rowg) v = -INFINITY;
                }
                sacc[j][e] = v;
            }

        float mt0 = -INFINITY, mt1 = -INFINITY;
#pragma unroll
        for (int j = 0; j < 8; j++) {
            mt0 = fmaxf(mt0, fmaxf(sacc[j][0], sacc[j][1]));
            mt1 = fmaxf(mt1, fmaxf(sacc[j][2], sacc[j][3]));
        }
        mt0 = fmaxf(mt0, __shfl_xor_sync(0xFFFFFFFFu, mt0, 1));
        mt0 = fmaxf(mt0, __shfl_xor_sync(0xFFFFFFFFu, mt0, 2));
        mt1 = fmaxf(mt1, __shfl_xor_sync(0xFFFFFFFFu, mt1, 1));
        mt1 = fmaxf(mt1, __shfl_xor_sync(0xFFFFFFFFu, mt1, 2));
        const float mn0 = fmaxf(m0, mt0), mn1 = fmaxf(m1, mt1);
        const float al0 = fexp2(m0 - mn0), al1 = fexp2(m1 - mn1);
        float s0 = 0.f, s1 = 0.f;
#pragma unroll
        for (int j = 0; j < 8; j++) {
            sacc[j][0] = fexp2(sacc[j][0] - mn0); s0 += sacc[j][0];
            sacc[j][1] = fexp2(sacc[j][1] - mn0); s0 += sacc[j][1];
            sacc[j][2] = fexp2(sacc[j][2] - mn1); s1 += sacc[j][2];
            sacc[j][3] = fexp2(sacc[j][3] - mn1); s1 += sacc[j][3];
        }
        s0 += __shfl_xor_sync(0xFFFFFFFFu, s0, 1);
        s0 += __shfl_xor_sync(0xFFFFFFFFu, s0, 2);
        s1 += __shfl_xor_sync(0xFFFFFFFFu, s1, 1);
        s1 += __shfl_xor_sync(0xFFFFFFFFu, s1, 2);
        l0 = l0 * al0 + s0;
        l1 = l1 * al1 + s1;
        m0 = mn0; m1 = mn1;
#pragma unroll
        for (int j = 0; j < 16; j++) {
            oacc[j][0] *= al0; oacc[j][1] *= al0;
            oacc[j][2] *= al1; oacc[j][3] *= al1;
        }

#pragma unroll
        for (int s2 = 0; s2 < 4; s2++) {
            uint32_t ph[4], pl[4];
            split2h(sacc[2 * s2][0],     sacc[2 * s2][1],     ph[0], pl[0]);
            split2h(sacc[2 * s2][2],     sacc[2 * s2][3],     ph[1], pl[1]);
            split2h(sacc[2 * s2 + 1][0], sacc[2 * s2 + 1][1], ph[2], pl[2]);
            split2h(sacc[2 * s2 + 1][2], sacc[2 * s2 + 1][3], ph[3], pl[3]);
            const int vrow = 16 * s2 + ((lane >> 3) & 1) * 8 + (lane & 7);
#pragma unroll
            for (int p = 0; p < 8; p++) {
                const uint32_t voff = (uint32_t)((p >> 2) * 8192) +
                    SW128((uint32_t)(vrow * 128 + 32 * (p & 3) + (lane >> 4) * 16));
                uint32_t r[4];
                ldsm4t(r, st + 16384 + voff);
                uint32_t b0[2] = { r[0], r[1] }, b1[2] = { r[2], r[3] };
                mma16816(oacc[2 * p],     ph, b0);
                mma16816(oacc[2 * p + 1], ph, b1);
                mma16816(oacc[2 * p],     pl, b0);
                mma16816(oacc[2 * p + 1], pl, b1);
            }
        }
        __syncthreads();
    }

    const float li0 = 1.f / l0, li1 = 1.f / l1;
    const int r0 = q0 + wm + (lane >> 2);
    const int cbase = h * HEAD_DIM + (lane & 3) * 2;
#pragma unroll
    for (int j = 0; j < 16; j++) {
        const size_t o0 = ((size_t)(b * SEQ + r0)) * D_MODEL + cbase + 8 * j;
        const size_t o1 = ((size_t)(b * SEQ + r0 + 8)) * D_MODEL + cbase + 8 * j;
        *(uint32_t*)&Ch[o0] = pack2h(oacc[j][0] * li0, oacc[j][1] * li0);
        *(uint32_t*)&Ch[o1] = pack2h(oacc[j][2] * li1, oacc[j][3] * li1);
    }
}

// ============================================================================
// launch
// ============================================================================
extern "C" void kernel_launch(void* const* d_in, const int* in_sizes, int n_in,
                              void* d_out, int out_size)
{
    const float* x  = (const float*)d_in[0];
    const float* wq = (const float*)d_in[1];
    const float* wk = (const float*)d_in[2];
    const float* wv = (const float*)d_in[3];
    const float* wo = (const float*)d_in[4];
    float* out = (float*)d_out;

    __half *xh, *xl, *wqh, *wkh, *wvh, *woh;
    __half *Qh, *Ql, *Kh, *Vh, *Ch;
    cudaGetSymbolAddress((void**)&xh, g_xh);
    cudaGetSymbolAddress((void**)&xl, g_xl);
    cudaGetSymbolAddress((void**)&wqh, g_wqh);
    cudaGetSymbolAddress((void**)&wkh, g_wkh);
    cudaGetSymbolAddress((void**)&wvh, g_wvh);
    cudaGetSymbolAddress((void**)&woh, g_woh);
    cudaGetSymbolAddress((void**)&Qh, g_Qh);
    cudaGetSymbolAddress((void**)&Ql, g_Ql);
    cudaGetSymbolAddress((void**)&Kh, g_Kh);
    cudaGetSymbolAddress((void**)&Vh, g_Vh);
    cudaGetSymbolAddress((void**)&Ch, g_Ch);

    cudaFuncSetAttribute(gemm_q_kernel,
                         cudaFuncAttributeMaxDynamicSharedMemorySize, GEMM_SMEM_2T);
    cudaFuncSetAttribute(gemm_kv_kernel,
                         cudaFuncAttributeMaxDynamicSharedMemorySize, GEMM_SMEM_1T);
    cudaFuncSetAttribute(gemm_o_kernel,
                         cudaFuncAttributeMaxDynamicSharedMemorySize, GEMM_SMEM_1T);
    cudaFuncSetAttribute(flash_mma_kernel,
                         cudaFuncAttributeMaxDynamicSharedMemorySize, FLASH_SMEM);

    const int nx4 = M_TOTAL * D_MODEL / 4;
    const int nw4 = D_MODEL * D_MODEL / 4;
    dim3 gg(D_MODEL / 128, M_TOTAL / 128);   // (16, 32)

    split_kernel<<<(nx4 + 255) / 256, 256>>>((const float4*)x, (uint2*)xh, (uint2*)xl, nx4);
    roundw_kernel<<<dim3((nw4 + 255) / 256, 4), 256>>>(
        (const float4*)wq, (const float4*)wk, (const float4*)wv, (const float4*)wo,
        (uint2*)wqh, (uint2*)wkh, (uint2*)wvh, (uint2*)woh, nw4);

    gemm_q_kernel<<<gg, 128, GEMM_SMEM_2T>>>(xh, xl, wqh, Qh, Ql);
    gemm_kv_kernel<<<dim3(gg.x, gg.y, 2), 128, GEMM_SMEM_1T>>>(xh, wkh, wvh, Kh, Vh);

    flash_mma_kernel<<<dim3(BATCH * NUM_HEADS, SEQ / TQF), 256, FLASH_SMEM>>>(
        Qh, Ql, Kh, Vh, Ch);

    gemm_o_kernel<<<gg, 128, GEMM_SMEM_1T>>>(Ch, woh, out);
}